// round 6
// baseline (speedup 1.0000x reference)
#include <cuda_runtime.h>
#include <cuda_bf16.h>
#include <cstdint>

// Problem constants
#define B_ 2
#define S_ 2048
#define E_ 2048
#define H_ 16
#define D_ 128
#define MROWS (B_ * S_)   // 4096

// ---------------------------------------------------------------------------
// Scratch (no cudaMalloc allowed)
// ---------------------------------------------------------------------------
__device__ float g_Q[(size_t)B_ * S_ * E_];
__device__ float g_K[(size_t)B_ * S_ * E_];
__device__ float g_V[(size_t)B_ * S_ * E_];
__device__ float g_C[(size_t)B_ * S_ * E_];
__device__ __nv_bfloat16 g_Ahi[(size_t)MROWS * E_];   // activations split
__device__ __nv_bfloat16 g_Alo[(size_t)MROWS * E_];
__device__ __nv_bfloat16 g_Whi[(size_t)E_ * E_];      // weights split, transposed [N][K]
__device__ __nv_bfloat16 g_Wlo[(size_t)E_ * E_];

// ---------------------------------------------------------------------------
// Helpers (all legal on base sm_103 target)
// ---------------------------------------------------------------------------
__device__ __forceinline__ uint32_t smem_u32(const void* p) {
    uint32_t a;
    asm("{ .reg .u64 t; cvta.to.shared.u64 t, %1; cvt.u32.u64 %0, t; }"
        : "=r"(a) : "l"(p));
    return a;
}

__device__ __forceinline__ void ldsm_x4(uint32_t* r, uint32_t addr) {
    asm volatile("ldmatrix.sync.aligned.m8n8.x4.shared.b16 {%0,%1,%2,%3}, [%4];"
        : "=r"(r[0]), "=r"(r[1]), "=r"(r[2]), "=r"(r[3]) : "r"(addr));
}
__device__ __forceinline__ void ldsm_x2(uint32_t* r, uint32_t addr) {
    asm volatile("ldmatrix.sync.aligned.m8n8.x2.shared.b16 {%0,%1}, [%2];"
        : "=r"(r[0]), "=r"(r[1]) : "r"(addr));
}
__device__ __forceinline__ void ldsm_x4t(uint32_t* r, uint32_t addr) {
    asm volatile("ldmatrix.sync.aligned.m8n8.x4.trans.shared.b16 {%0,%1,%2,%3}, [%4];"
        : "=r"(r[0]), "=r"(r[1]), "=r"(r[2]), "=r"(r[3]) : "r"(addr));
}

// D += A(16x16 bf16) * B(16x8 bf16), fp32 accum
__device__ __forceinline__ void mma16816(float* c, const uint32_t* a, const uint32_t* b) {
    asm volatile(
        "mma.sync.aligned.m16n8k16.row.col.f32.bf16.bf16.f32 "
        "{%0,%1,%2,%3}, {%4,%5,%6,%7}, {%8,%9}, {%0,%1,%2,%3};"
        : "+f"(c[0]), "+f"(c[1]), "+f"(c[2]), "+f"(c[3])
        : "r"(a[0]), "r"(a[1]), "r"(a[2]), "r"(a[3]), "r"(b[0]), "r"(b[1]));
}

__device__ __forceinline__ float ex2f(float x) {
    float y; asm("ex2.approx.f32 %0, %1;" : "=f"(y) : "f"(x)); return y;
}

// pack two fp32 -> bf16x2 (low = a, high = b)
__device__ __forceinline__ uint32_t packbf(float a, float b) {
    uint32_t r; asm("cvt.rn.bf16x2.f32 %0, %1, %2;" : "=r"(r) : "f"(b), "f"(a));
    return r;
}

// split float4 into hi/lo bf16x2 pairs
__device__ __forceinline__ void split4(float4 v, uint2& hi, uint2& lo) {
    uint32_t h0 = packbf(v.x, v.y), h1 = packbf(v.z, v.w);
    float a0 = __uint_as_float(h0 << 16), a1 = __uint_as_float(h0 & 0xffff0000u);
    float a2 = __uint_as_float(h1 << 16), a3 = __uint_as_float(h1 & 0xffff0000u);
    hi.x = h0; hi.y = h1;
    lo.x = packbf(v.x - a0, v.y - a1);
    lo.y = packbf(v.z - a2, v.w - a3);
}

__device__ __forceinline__ void cpasync16(uint32_t saddr, const void* g) {
    asm volatile("cp.async.cg.shared.global [%0], [%1], 16;"
        :: "r"(saddr), "l"(g));
}
#define CP_COMMIT() asm volatile("cp.async.commit_group;" ::: "memory")
#define CP_WAIT1()  asm volatile("cp.async.wait_group 1;" ::: "memory")
#define CP_WAIT0()  asm volatile("cp.async.wait_group 0;" ::: "memory")

#define SMEM_SWIZZLE_128B(off) ((off) ^ (((off) >> 3) & 0x70))

// ---------------------------------------------------------------------------
// Split fp32 activations into (hi, lo) bf16, same layout [M][K]
// ---------------------------------------------------------------------------
__global__ void __launch_bounds__(256) splitA_kernel(
    const float* __restrict__ x, __nv_bfloat16* __restrict__ hi,
    __nv_bfloat16* __restrict__ lo)
{
    size_t i = (size_t)blockIdx.x * 256 + threadIdx.x;  // one float4
    float4 v = ((const float4*)x)[i];
    uint2 h, l;
    split4(v, h, l);
    ((uint2*)hi)[i] = h;
    ((uint2*)lo)[i] = l;
}

// ---------------------------------------------------------------------------
// Transpose + split fp32 weights W[K][N] -> hi/lo bf16 [N][K]
// ---------------------------------------------------------------------------
__global__ void __launch_bounds__(256) convW_kernel(
    const float* __restrict__ W, __nv_bfloat16* __restrict__ hi,
    __nv_bfloat16* __restrict__ lo)
{
    __shared__ float t[32][33];
    int tx = threadIdx.x & 31, ty = threadIdx.x >> 5;  // 32 x 8
    int nb = blockIdx.x * 32, kb = blockIdx.y * 32;
    #pragma unroll
    for (int i = 0; i < 4; ++i) {
        int k = kb + ty + i * 8;
        t[ty + i * 8][tx] = W[(size_t)k * E_ + nb + tx];
    }
    __syncthreads();
    #pragma unroll
    for (int i = 0; i < 4; ++i) {
        int n = nb + ty + i * 8;
        float v = t[tx][ty + i * 8];
        __nv_bfloat16 h = __float2bfloat16(v);
        hi[(size_t)n * E_ + kb + tx] = h;
        lo[(size_t)n * E_ + kb + tx] = __float2bfloat16(v - __bfloat162float(h));
    }
}

// ---------------------------------------------------------------------------
// mma.sync split-bf16 GEMM with 2-stage cp.async pipeline.
//   C[M,N] = A[M,K] * B[N,K]^T + bias
//   128x128 CTA tile, BK=64, 8 warps (2x4), 64x32 warp tile.
//   D = Ahi*Bhi + Ahi*Blo + Alo*Bhi  (fp32 accumulate)
//   Stage = 4 swizzled [128][64] bf16 tiles = 64KB; 2 stages = 128KB smem.
// ---------------------------------------------------------------------------
#define GEMM_STAGE 65536
#define GEMM_SMEM (2 * GEMM_STAGE)
#define NKC 32   // K / 64

__global__ void __launch_bounds__(256) gemm_mma_kernel(
    const __nv_bfloat16* __restrict__ Ahi, const __nv_bfloat16* __restrict__ Alo,
    const __nv_bfloat16* __restrict__ Bhi, const __nv_bfloat16* __restrict__ Blo,
    const float* __restrict__ bias, float* __restrict__ C)
{
    extern __shared__ char smc[];
    const uint32_t sb = smem_u32(smc);

    const int tid  = threadIdx.x;
    const int wid  = tid >> 5;
    const int lane = tid & 31;
    const int bx = blockIdx.x;   // N tile (16)
    const int by = blockIdx.y;   // M tile (32)

    const int warpM = (wid >> 2) * 64;   // 0 or 64
    const int warpN = (wid & 3) * 32;    // 0,32,64,96

    const size_t aRow0 = (size_t)by * 128;
    const size_t bRow0 = (size_t)bx * 128;

    // cp.async addressing (per thread: 4 rows x 4 arrays, 16B each)
    const int ldR = tid >> 3;       // 0..31 base row
    const int ldS = tid & 7;        // 16B column chunk
    const uint32_t ldOff0 = SMEM_SWIZZLE_128B((uint32_t)(ldR * 128 + ldS * 16));

    float acc[4][4][4];
    #pragma unroll
    for (int mi = 0; mi < 4; ++mi)
        #pragma unroll
        for (int ni = 0; ni < 4; ++ni)
            #pragma unroll
            for (int j = 0; j < 4; ++j) acc[mi][ni][j] = 0.f;

    const uint32_t aRowL = warpM + (lane & 15);
    const uint32_t aColL = (lane >> 4) * 8;
    const uint32_t bRowL = warpN + (lane & 7);
    const uint32_t bColL = ((lane >> 3) & 1) * 8;

    // ---- stage loader ----
    auto load_stage = [&](int kc, int st) {
        const int k0 = kc * 64;
        const uint32_t base = sb + st * GEMM_STAGE;
        #pragma unroll
        for (int it = 0; it < 4; ++it) {
            const int r = ldR + it * 32;
            const uint32_t off = (it & 1) ? (ldOff0 ^ 0x1000u) : ldOff0;  // row+32 flips bit12? no—recompute
            (void)off;
            const uint32_t o = SMEM_SWIZZLE_128B((uint32_t)(r * 128 + ldS * 16));
            const __nv_bfloat16* gah = Ahi + (aRow0 + r) * E_ + k0 + ldS * 8;
            const __nv_bfloat16* gal = Alo + (aRow0 + r) * E_ + k0 + ldS * 8;
            const __nv_bfloat16* gbh = Bhi + (bRow0 + r) * E_ + k0 + ldS * 8;
            const __nv_bfloat16* gbl = Blo + (bRow0 + r) * E_ + k0 + ldS * 8;
            cpasync16(base + o,         gah);
            cpasync16(base + 16384 + o, gal);
            cpasync16(base + 32768 + o, gbh);
            cpasync16(base + 49152 + o, gbl);
        }
    };

    // prologue: 2 stages in flight
    load_stage(0, 0); CP_COMMIT();
    load_stage(1, 1); CP_COMMIT();

    for (int kc = 0; kc < NKC; ++kc) {
        if (kc == NKC - 1) { CP_WAIT0(); } else { CP_WAIT1(); }
        __syncthreads();

        const uint32_t SAH = sb + (kc & 1) * GEMM_STAGE;
        const uint32_t SAL = SAH + 16384;
        const uint32_t SBH = SAH + 32768;
        const uint32_t SBL = SAH + 49152;

        #pragma unroll
        for (int ks = 0; ks < 4; ++ks) {
            const uint32_t kb = ks * 16;
            uint32_t ah[4][4], al[4][4], bh[4][2], bl[4][2];
            #pragma unroll
            for (int mi = 0; mi < 4; ++mi) {
                uint32_t off = (aRowL + mi * 16) * 128 + (kb + aColL) * 2;
                off = SMEM_SWIZZLE_128B(off);
                ldsm_x4(ah[mi], SAH + off);
                ldsm_x4(al[mi], SAL + off);
            }
            #pragma unroll
            for (int ni = 0; ni < 4; ++ni) {
                uint32_t off = (bRowL + ni * 8) * 128 + (kb + bColL) * 2;
                off = SMEM_SWIZZLE_128B(off);
                ldsm_x2(bh[ni], SBH + off);
                ldsm_x2(bl[ni], SBL + off);
            }
            #pragma unroll
            for (int mi = 0; mi < 4; ++mi)
                #pragma unroll
                for (int ni = 0; ni < 4; ++ni) {
                    mma16816(acc[mi][ni], ah[mi], bh[ni]);
                    mma16816(acc[mi][ni], ah[mi], bl[ni]);
                    mma16816(acc[mi][ni], al[mi], bh[ni]);
                }
        }
        __syncthreads();   // all warps done reading this stage
        if (kc + 2 < NKC) { load_stage(kc + 2, kc & 1); CP_COMMIT(); }
    }

    // Epilogue: c0,c1 -> (row, col..col+1); c2,c3 -> (row+8, col..col+1)
    const int rQuad = lane >> 2;
    const int cPair = (lane & 3) * 2;
    #pragma unroll
    for (int mi = 0; mi < 4; ++mi) {
        #pragma unroll
        for (int ni = 0; ni < 4; ++ni) {
            int row = by * 128 + warpM + mi * 16 + rQuad;
            int col = bx * 128 + warpN + ni * 8 + cPair;
            float b0 = bias[col], b1 = bias[col + 1];
            float2 v0 = make_float2(acc[mi][ni][0] + b0, acc[mi][ni][1] + b1);
            float2 v1 = make_float2(acc[mi][ni][2] + b0, acc[mi][ni][3] + b1);
            *(float2*)(C + (size_t)row * E_ + col)       = v0;
            *(float2*)(C + (size_t)(row + 8) * E_ + col) = v1;
        }
    }
}

// ---------------------------------------------------------------------------
// Tensor-core flash attention, split-bf16 (3-term) for QK^T and PV.
// (unchanged from Round 5 — validated)
// ---------------------------------------------------------------------------
#define FL_QH 0
#define FL_QL 16384
#define FL_KH 32768
#define FL_KL 49152
#define FL_VH 65536
#define FL_VL 81920
#define FL2_SMEM 98304

__global__ void __launch_bounds__(128) flash_mma_kernel(
    const float* __restrict__ Qg, const float* __restrict__ Kg,
    const float* __restrict__ Vg, float* __restrict__ Ctx)
{
    extern __shared__ char sm[];
    const uint32_t sb = smem_u32(sm);

    const int qt = blockIdx.x, h = blockIdx.y, b = blockIdx.z;
    const int tid = threadIdx.x, w = tid >> 5, lane = tid & 31;
    const float SCALE = 0.08838834764831845f;   // 1/sqrt(128)
    const float L2E = 1.4426950408889634f;

    const float* Qbase = Qg + ((size_t)b * S_ + qt * 64) * E_ + h * D_;

    for (int i = tid; i < 64 * 32; i += 128) {
        int r = i >> 5, c4 = (i & 31) * 4;
        float4 v = *(const float4*)(Qbase + (size_t)r * E_ + c4);
        v.x *= SCALE; v.y *= SCALE; v.z *= SCALE; v.w *= SCALE;
        uint2 hi, lo;
        split4(v, hi, lo);
        uint32_t off = SMEM_SWIZZLE_128B((uint32_t)(r * 128 + (c4 & 63) * 2));
        uint32_t subo = (c4 >> 6) * 8192;
        *(uint2*)(sm + FL_QH + subo + off) = hi;
        *(uint2*)(sm + FL_QL + subo + off) = lo;
    }

    float oacc[16][4];
    #pragma unroll
    for (int f = 0; f < 16; ++f)
        #pragma unroll
        for (int j = 0; j < 4; ++j) oacc[f][j] = 0.f;
    float m0 = -1e30f, m1 = -1e30f, l0 = 0.f, l1 = 0.f;

    const uint32_t aRowL = w * 16 + (lane & 15);
    const uint32_t aColL = (lane >> 4) * 8;
    const uint32_t bRowL = lane & 7;
    const uint32_t bColL = ((lane >> 3) & 1) * 8;
    const uint32_t vR = lane & 7, vM = lane >> 3;

    for (int kt = 0; kt < 32; ++kt) {
        __syncthreads();
        const float* Kb = Kg + ((size_t)b * S_ + kt * 64) * E_ + h * D_;
        const float* Vb = Vg + ((size_t)b * S_ + kt * 64) * E_ + h * D_;
        for (int i = tid; i < 64 * 32; i += 128) {
            int r = i >> 5, c4 = (i & 31) * 4;
            uint32_t off = SMEM_SWIZZLE_128B((uint32_t)(r * 128 + (c4 & 63) * 2));
            uint32_t subo = (c4 >> 6) * 8192;
            float4 kv = *(const float4*)(Kb + (size_t)r * E_ + c4);
            uint2 hi, lo;
            split4(kv, hi, lo);
            *(uint2*)(sm + FL_KH + subo + off) = hi;
            *(uint2*)(sm + FL_KL + subo + off) = lo;
            float4 vv = *(const float4*)(Vb + (size_t)r * E_ + c4);
            split4(vv, hi, lo);
            *(uint2*)(sm + FL_VH + subo + off) = hi;
            *(uint2*)(sm + FL_VL + subo + off) = lo;
        }
        __syncthreads();

        float sacc[8][4];
        #pragma unroll
        for (int ni = 0; ni < 8; ++ni)
            #pragma unroll
            for (int j = 0; j < 4; ++j) sacc[ni][j] = 0.f;

        #pragma unroll
        for (int half = 0; half < 2; ++half) {
            #pragma unroll
            for (int ks = 0; ks < 4; ++ks) {
                const uint32_t kb = ks * 16;
                uint32_t ah[4], al[4];
                uint32_t aoff = SMEM_SWIZZLE_128B(aRowL * 128 + (kb + aColL) * 2);
                ldsm_x4(ah, sb + FL_QH + half * 8192 + aoff);
                ldsm_x4(al, sb + FL_QL + half * 8192 + aoff);
                #pragma unroll
                for (int ni = 0; ni < 8; ++ni) {
                    uint32_t bh[2], bl[2];
                    uint32_t boff = SMEM_SWIZZLE_128B((bRowL + ni * 8) * 128 + (kb + bColL) * 2);
                    ldsm_x2(bh, sb + FL_KH + half * 8192 + boff);
                    ldsm_x2(bl, sb + FL_KL + half * 8192 + boff);
                    mma16816(sacc[ni], ah, bh);
                    mma16816(sacc[ni], ah, bl);
                    mma16816(sacc[ni], al, bh);
                }
            }
        }

        float mx0 = -1e30f, mx1 = -1e30f;
        #pragma unroll
        for (int ni = 0; ni < 8; ++ni) {
            mx0 = fmaxf(mx0, fmaxf(sacc[ni][0], sacc[ni][1]));
            mx1 = fmaxf(mx1, fmaxf(sacc[ni][2], sacc[ni][3]));
        }
        mx0 = fmaxf(mx0, __shfl_xor_sync(0xffffffffu, mx0, 1));
        mx0 = fmaxf(mx0, __shfl_xor_sync(0xffffffffu, mx0, 2));
        mx1 = fmaxf(mx1, __shfl_xor_sync(0xffffffffu, mx1, 1));
        mx1 = fmaxf(mx1, __shfl_xor_sync(0xffffffffu, mx1, 2));
        const float mn0 = fmaxf(m0, mx0), mn1 = fmaxf(m1, mx1);
        const float al0 = ex2f((m0 - mn0) * L2E), al1 = ex2f((m1 - mn1) * L2E);
        m0 = mn0; m1 = mn1;

        uint32_t ph[8][2], pl[8][2];
        float ls0 = 0.f, ls1 = 0.f;
        #pragma unroll
        for (int ni = 0; ni < 8; ++ni) {
            float p00 = ex2f((sacc[ni][0] - mn0) * L2E);
            float p01 = ex2f((sacc[ni][1] - mn0) * L2E);
            float p10 = ex2f((sacc[ni][2] - mn1) * L2E);
            float p11 = ex2f((sacc[ni][3] - mn1) * L2E);
            ls0 += p00 + p01;
            ls1 += p10 + p11;
            uint32_t hp0 = packbf(p00, p01);
            uint32_t hp1 = packbf(p10, p11);
            float h00 = __uint_as_float(hp0 << 16);
            float h01 = __uint_as_float(hp0 & 0xffff0000u);
            float h10 = __uint_as_float(hp1 << 16);
            float h11 = __uint_as_float(hp1 & 0xffff0000u);
            ph[ni][0] = hp0;
            ph[ni][1] = hp1;
            pl[ni][0] = packbf(p00 - h00, p01 - h01);
            pl[ni][1] = packbf(p10 - h10, p11 - h11);
        }
        ls0 += __shfl_xor_sync(0xffffffffu, ls0, 1);
        ls0 += __shfl_xor_sync(0xffffffffu, ls0, 2);
        ls1 += __shfl_xor_sync(0xffffffffu, ls1, 1);
        ls1 += __shfl_xor_sync(0xffffffffu, ls1, 2);
        l0 = l0 * al0 + ls0;
        l1 = l1 * al1 + ls1;

        #pragma unroll
        for (int f = 0; f < 16; ++f) {
            oacc[f][0] *= al0; oacc[f][1] *= al0;
            oacc[f][2] *= al1; oacc[f][3] *= al1;
        }

        #pragma unroll
        for (int kf = 0; kf < 4; ++kf) {
            uint32_t aPh[4] = { ph[2*kf][0], ph[2*kf][1], ph[2*kf+1][0], ph[2*kf+1][1] };
            uint32_t aPl[4] = { pl[2*kf][0], pl[2*kf][1], pl[2*kf+1][0], pl[2*kf+1][1] };
            #pragma unroll
            for (int nd = 0; nd < 8; ++nd) {
                const uint32_t sub = (nd >> 2) * 8192;
                const uint32_t dd = (nd & 3) * 16;
                const uint32_t kvr = kf * 16 + (vM & 1) * 8 + vR;
                const uint32_t dc = dd + (vM >> 1) * 8;
                const uint32_t voff = SMEM_SWIZZLE_128B(kvr * 128 + dc * 2);
                uint32_t bh4[4], bl4[4];
                ldsm_x4t(bh4, sb + FL_VH + sub + voff);
                ldsm_x4t(bl4, sb + FL_VL + sub + voff);
                mma16816(oacc[2*nd],     aPh, bh4);
                mma16816(oacc[2*nd],     aPh, bl4);
                mma16816(oacc[2*nd],     aPl, bh4);
                mma16816(oacc[2*nd + 1], aPh, bh4 + 2);
                mma16816(oacc[2*nd + 1], aPh, bl4 + 2);
                mma16816(oacc[2*nd + 1], aPl, bh4 + 2);
            }
        }
    }

    const float inv0 = 1.f / l0, inv1 = 1.f / l1;
    const int rQuad = lane >> 2, cPair = (lane & 3) * 2;
    float* op = Ctx + ((size_t)b * S_ + qt * 64 + w * 16 + rQuad) * E_ + h * D_;
    #pragma unroll
    for (int f = 0; f < 16; ++f) {
        int d = f * 8 + cPair;
        *(float2*)(op + d) = make_float2(oacc[f][0] * inv0, oacc[f][1] * inv0);
        *(float2*)(op + 8 * E_ + d) = make_float2(oacc[f][2] * inv1, oacc[f][3] * inv1);
    }
}

// ---------------------------------------------------------------------------
extern "C" void kernel_launch(void* const* d_in, const int* in_sizes, int n_in,
                              void* d_out, int out_size)
{
    const float* query  = (const float*)d_in[0];
    const float* key_in = (const float*)d_in[1];
    const float* value  = (const float*)d_in[2];
    const float* Wq = (const float*)d_in[3];
    const float* bq = (const float*)d_in[4];
    const float* Wk = (const float*)d_in[5];
    const float* bk = (const float*)d_in[6];
    const float* Wv = (const float*)d_in[7];
    const float* bv = (const float*)d_in[8];
    const float* Wo = (const float*)d_in[9];
    const float* bo = (const float*)d_in[10];
    float* out = (float*)d_out;

    float *Qb, *Kb, *Vb, *Cb;
    __nv_bfloat16 *Ahi, *Alo, *Whi, *Wlo;
    cudaGetSymbolAddress((void**)&Qb, g_Q);
    cudaGetSymbolAddress((void**)&Kb, g_K);
    cudaGetSymbolAddress((void**)&Vb, g_V);
    cudaGetSymbolAddress((void**)&Cb, g_C);
    cudaGetSymbolAddress((void**)&Ahi, g_Ahi);
    cudaGetSymbolAddress((void**)&Alo, g_Alo);
    cudaGetSymbolAddress((void**)&Whi, g_Whi);
    cudaGetSymbolAddress((void**)&Wlo, g_Wlo);

    cudaFuncSetAttribute(flash_mma_kernel,
                         cudaFuncAttributeMaxDynamicSharedMemorySize,
                         FL2_SMEM);
    cudaFuncSetAttribute(gemm_mma_kernel,
                         cudaFuncAttributeMaxDynamicSharedMemorySize,
                         GEMM_SMEM);

    const dim3 cw(E_ / 32, E_ / 32);            // convW tiles
    const int  sa = (MROWS * E_ / 4) / 256;     // splitA blocks (8192)
    const dim3 gg(E_ / 128, MROWS / 128);       // gemm tiles (16, 32)
    const dim3 fg(S_ / 64, H_, B_);             // flash (32, 16, 2)

    // Q projection
    convW_kernel<<<cw, 256>>>(Wq, Whi, Wlo);
    splitA_kernel<<<sa, 256>>>(query, Ahi, Alo);
    gemm_mma_kernel<<<gg, 256, GEMM_SMEM>>>(Ahi, Alo, Whi, Wlo, bq, Qb);
    // K projection
    convW_kernel<<<cw, 256>>>(Wk, Whi, Wlo);
    splitA_kernel<<<sa, 256>>>(key_in, Ahi, Alo);
    gemm_mma_kernel<<<gg, 256, GEMM_SMEM>>>(Ahi, Alo, Whi, Wlo, bk, Kb);
    // V projection
    convW_kernel<<<cw, 256>>>(Wv, Whi, Wlo);
    splitA_kernel<<<sa, 256>>>(value, Ahi, Alo);
    gemm_mma_kernel<<<gg, 256, GEMM_SMEM>>>(Ahi, Alo, Whi, Wlo, bv, Vb);
    // Attention (tensor-core flash)
    flash_mma_kernel<<<fg, 128, FL2_SMEM>>>(Qb, Kb, Vb, Cb);
    // Output projection
    convW_kernel<<<cw, 256>>>(Wo, Whi, Wlo);
    splitA_kernel<<<sa, 256>>>(Cb, Ahi, Alo);
    gemm_mma_kernel<<<gg, 256, GEMM_SMEM>>>(Ahi, Alo, Whi, Wlo, bo, out);
}

// round 7
// speedup vs baseline: 1.1164x; 1.1164x over previous
#include <cuda_runtime.h>
#include <cuda_bf16.h>
#include <cstdint>

// Problem constants
#define B_ 2
#define S_ 2048
#define E_ 2048
#define H_ 16
#define D_ 128
#define MROWS (B_ * S_)   // 4096

// ---------------------------------------------------------------------------
// Scratch (no cudaMalloc allowed) — all bf16 split pairs
// ---------------------------------------------------------------------------
__device__ __nv_bfloat16 g_Ahi[(size_t)MROWS * E_];
__device__ __nv_bfloat16 g_Alo[(size_t)MROWS * E_];
__device__ __nv_bfloat16 g_Whi[(size_t)E_ * E_];
__device__ __nv_bfloat16 g_Wlo[(size_t)E_ * E_];
__device__ __nv_bfloat16 g_Qhi[(size_t)MROWS * E_];
__device__ __nv_bfloat16 g_Qlo[(size_t)MROWS * E_];
__device__ __nv_bfloat16 g_Khi[(size_t)MROWS * E_];
__device__ __nv_bfloat16 g_Klo[(size_t)MROWS * E_];
__device__ __nv_bfloat16 g_Vhi[(size_t)MROWS * E_];
__device__ __nv_bfloat16 g_Vlo[(size_t)MROWS * E_];
__device__ __nv_bfloat16 g_Chi[(size_t)MROWS * E_];
__device__ __nv_bfloat16 g_Clo[(size_t)MROWS * E_];

// ---------------------------------------------------------------------------
// Helpers (legal on base sm_103 target)
// ---------------------------------------------------------------------------
__device__ __forceinline__ uint32_t smem_u32(const void* p) {
    uint32_t a;
    asm("{ .reg .u64 t; cvta.to.shared.u64 t, %1; cvt.u32.u64 %0, t; }"
        : "=r"(a) : "l"(p));
    return a;
}
__device__ __forceinline__ void ldsm_x4(uint32_t* r, uint32_t addr) {
    asm volatile("ldmatrix.sync.aligned.m8n8.x4.shared.b16 {%0,%1,%2,%3}, [%4];"
        : "=r"(r[0]), "=r"(r[1]), "=r"(r[2]), "=r"(r[3]) : "r"(addr));
}
__device__ __forceinline__ void ldsm_x2(uint32_t* r, uint32_t addr) {
    asm volatile("ldmatrix.sync.aligned.m8n8.x2.shared.b16 {%0,%1}, [%2];"
        : "=r"(r[0]), "=r"(r[1]) : "r"(addr));
}
__device__ __forceinline__ void ldsm_x4t(uint32_t* r, uint32_t addr) {
    asm volatile("ldmatrix.sync.aligned.m8n8.x4.trans.shared.b16 {%0,%1,%2,%3}, [%4];"
        : "=r"(r[0]), "=r"(r[1]), "=r"(r[2]), "=r"(r[3]) : "r"(addr));
}
__device__ __forceinline__ void mma16816(float* c, const uint32_t* a, const uint32_t* b) {
    asm volatile(
        "mma.sync.aligned.m16n8k16.row.col.f32.bf16.bf16.f32 "
        "{%0,%1,%2,%3}, {%4,%5,%6,%7}, {%8,%9}, {%0,%1,%2,%3};"
        : "+f"(c[0]), "+f"(c[1]), "+f"(c[2]), "+f"(c[3])
        : "r"(a[0]), "r"(a[1]), "r"(a[2]), "r"(a[3]), "r"(b[0]), "r"(b[1]));
}
__device__ __forceinline__ float ex2f(float x) {
    float y; asm("ex2.approx.f32 %0, %1;" : "=f"(y) : "f"(x)); return y;
}
__device__ __forceinline__ uint32_t packbf(float a, float b) {
    uint32_t r; asm("cvt.rn.bf16x2.f32 %0, %1, %2;" : "=r"(r) : "f"(b), "f"(a));
    return r;
}
__device__ __forceinline__ float lobf(uint32_t p)  { return __uint_as_float(p << 16); }
__device__ __forceinline__ float hibf(uint32_t p)  { return __uint_as_float(p & 0xffff0000u); }

__device__ __forceinline__ void split4(float4 v, uint2& hi, uint2& lo) {
    uint32_t h0 = packbf(v.x, v.y), h1 = packbf(v.z, v.w);
    hi.x = h0; hi.y = h1;
    lo.x = packbf(v.x - lobf(h0), v.y - hibf(h0));
    lo.y = packbf(v.z - lobf(h1), v.w - hibf(h1));
}

__device__ __forceinline__ void cpasync16(uint32_t saddr, const void* g) {
    asm volatile("cp.async.cg.shared.global [%0], [%1], 16;" :: "r"(saddr), "l"(g));
}
#define CP_COMMIT() asm volatile("cp.async.commit_group;" ::: "memory")
#define CP_WAIT1()  asm volatile("cp.async.wait_group 1;" ::: "memory")
#define CP_WAIT0()  asm volatile("cp.async.wait_group 0;" ::: "memory")

#define SMEM_SWIZZLE_128B(off) ((off) ^ (((off) >> 3) & 0x70))

// ---------------------------------------------------------------------------
// Split fp32 activations into (hi, lo) bf16, same layout [M][K]
// ---------------------------------------------------------------------------
__global__ void __launch_bounds__(256) splitA_kernel(
    const float* __restrict__ x, __nv_bfloat16* __restrict__ hi,
    __nv_bfloat16* __restrict__ lo)
{
    size_t i = (size_t)blockIdx.x * 256 + threadIdx.x;
    float4 v = ((const float4*)x)[i];
    uint2 h, l;
    split4(v, h, l);
    ((uint2*)hi)[i] = h;
    ((uint2*)lo)[i] = l;
}

// ---------------------------------------------------------------------------
// Transpose + split fp32 weights W[K][N] -> hi/lo bf16 [N][K]
// ---------------------------------------------------------------------------
__global__ void __launch_bounds__(256) convW_kernel(
    const float* __restrict__ W, __nv_bfloat16* __restrict__ hi,
    __nv_bfloat16* __restrict__ lo)
{
    __shared__ float t[32][33];
    int tx = threadIdx.x & 31, ty = threadIdx.x >> 5;
    int nb = blockIdx.x * 32, kb = blockIdx.y * 32;
    #pragma unroll
    for (int i = 0; i < 4; ++i) {
        int k = kb + ty + i * 8;
        t[ty + i * 8][tx] = W[(size_t)k * E_ + nb + tx];
    }
    __syncthreads();
    #pragma unroll
    for (int i = 0; i < 4; ++i) {
        int n = nb + ty + i * 8;
        float v = t[tx][ty + i * 8];
        __nv_bfloat16 h = __float2bfloat16(v);
        hi[(size_t)n * E_ + kb + tx] = h;
        lo[(size_t)n * E_ + kb + tx] = __float2bfloat16(v - __bfloat162float(h));
    }
}

// ---------------------------------------------------------------------------
// mma.sync split-bf16 GEMM (R5 synchronous mainloop, 64KB smem, 3 CTA/SM).
// Templated epilogue: SPLIT=false -> fp32 C; SPLIT=true -> hi/lo bf16.
// ---------------------------------------------------------------------------
#define GEMM_SMEM (4 * 16384)

template <bool SPLIT>
__global__ void __launch_bounds__(256) gemm_mma_kernel(
    const __nv_bfloat16* __restrict__ Ahi, const __nv_bfloat16* __restrict__ Alo,
    const __nv_bfloat16* __restrict__ Bhi, const __nv_bfloat16* __restrict__ Blo,
    const float* __restrict__ bias, float* __restrict__ C,
    __nv_bfloat16* __restrict__ Chi, __nv_bfloat16* __restrict__ Clo)
{
    extern __shared__ char smc[];
    const uint32_t sb  = smem_u32(smc);
    const uint32_t SAH = sb;
    const uint32_t SAL = sb + 16384;
    const uint32_t SBH = sb + 32768;
    const uint32_t SBL = sb + 49152;

    const int tid  = threadIdx.x;
    const int wid  = tid >> 5;
    const int lane = tid & 31;
    const int bx = blockIdx.x;
    const int by = blockIdx.y;

    const int warpM = (wid >> 2) * 64;
    const int warpN = (wid & 3) * 32;

    const size_t aRow0 = (size_t)by * 128;
    const size_t bRow0 = (size_t)bx * 128;

    float acc[4][4][4];
    #pragma unroll
    for (int mi = 0; mi < 4; ++mi)
        #pragma unroll
        for (int ni = 0; ni < 4; ++ni)
            #pragma unroll
            for (int j = 0; j < 4; ++j) acc[mi][ni][j] = 0.f;

    const uint32_t aRowL = warpM + (lane & 15);
    const uint32_t aColL = (lane >> 4) * 8;
    const uint32_t bRowL = warpN + (lane & 7);
    const uint32_t bColL = ((lane >> 3) & 1) * 8;

    for (int kc = 0; kc < 32; ++kc) {
        const int k0 = kc * 64;
        __syncthreads();
        #pragma unroll
        for (int it = 0; it < 4; ++it) {
            int idx = tid + it * 256;
            int r = idx >> 3;
            int s = idx & 7;
            uint32_t off = SMEM_SWIZZLE_128B((uint32_t)(r * 128 + s * 16));
            const uint4* pah = (const uint4*)(Ahi + (aRow0 + r) * E_ + k0);
            const uint4* pal = (const uint4*)(Alo + (aRow0 + r) * E_ + k0);
            const uint4* pbh = (const uint4*)(Bhi + (bRow0 + r) * E_ + k0);
            const uint4* pbl = (const uint4*)(Blo + (bRow0 + r) * E_ + k0);
            *(uint4*)(smc + off)         = pah[s];
            *(uint4*)(smc + 16384 + off) = pal[s];
            *(uint4*)(smc + 32768 + off) = pbh[s];
            *(uint4*)(smc + 49152 + off) = pbl[s];
        }
        __syncthreads();

        #pragma unroll
        for (int ks = 0; ks < 4; ++ks) {
            const uint32_t kb = ks * 16;
            uint32_t ah[4][4], al[4][4], bh[4][2], bl[4][2];
            #pragma unroll
            for (int mi = 0; mi < 4; ++mi) {
                uint32_t off = (aRowL + mi * 16) * 128 + (kb + aColL) * 2;
                off = SMEM_SWIZZLE_128B(off);
                ldsm_x4(ah[mi], SAH + off);
                ldsm_x4(al[mi], SAL + off);
            }
            #pragma unroll
            for (int ni = 0; ni < 4; ++ni) {
                uint32_t off = (bRowL + ni * 8) * 128 + (kb + bColL) * 2;
                off = SMEM_SWIZZLE_128B(off);
                ldsm_x2(bh[ni], SBH + off);
                ldsm_x2(bl[ni], SBL + off);
            }
            #pragma unroll
            for (int mi = 0; mi < 4; ++mi)
                #pragma unroll
                for (int ni = 0; ni < 4; ++ni) {
                    mma16816(acc[mi][ni], ah[mi], bh[ni]);
                    mma16816(acc[mi][ni], ah[mi], bl[ni]);
                    mma16816(acc[mi][ni], al[mi], bh[ni]);
                }
        }
    }

    const int rQuad = lane >> 2;
    const int cPair = (lane & 3) * 2;
    #pragma unroll
    for (int mi = 0; mi < 4; ++mi) {
        #pragma unroll
        for (int ni = 0; ni < 4; ++ni) {
            int row = by * 128 + warpM + mi * 16 + rQuad;
            int col = bx * 128 + warpN + ni * 8 + cPair;
            float b0 = bias[col], b1 = bias[col + 1];
            float o00 = acc[mi][ni][0] + b0, o01 = acc[mi][ni][1] + b1;
            float o10 = acc[mi][ni][2] + b0, o11 = acc[mi][ni][3] + b1;
            if constexpr (SPLIT) {
                size_t i0 = ((size_t)row * E_ + col) >> 1;
                size_t i1 = ((size_t)(row + 8) * E_ + col) >> 1;
                uint32_t h0 = packbf(o00, o01);
                uint32_t h1 = packbf(o10, o11);
                ((uint32_t*)Chi)[i0] = h0;
                ((uint32_t*)Chi)[i1] = h1;
                ((uint32_t*)Clo)[i0] = packbf(o00 - lobf(h0), o01 - hibf(h0));
                ((uint32_t*)Clo)[i1] = packbf(o10 - lobf(h1), o11 - hibf(h1));
            } else {
                *(float2*)(C + (size_t)row * E_ + col)       = make_float2(o00, o01);
                *(float2*)(C + (size_t)(row + 8) * E_ + col) = make_float2(o10, o11);
            }
        }
    }
}

// ---------------------------------------------------------------------------
// Tensor-core flash attention, BM=128 (8 warps), pre-split bf16 inputs,
// 2-stage cp.async KV pipeline, split bf16 output.
// Smem: Q hi/lo [128][128] = 64KB  +  2 stages x (K,V hi/lo [64][128]) = 128KB
// ---------------------------------------------------------------------------
#define FQ_H   0        // Qh: half0 @0, half1 @16384
#define FQ_L   32768
#define FKV0   65536
#define KV_STAGE 65536
#define KV_KH  0
#define KV_KL  16384
#define KV_VH  32768
#define KV_VL  49152
#define FL_SMEM 196608

__global__ void __launch_bounds__(256) flash_mma_kernel(
    const __nv_bfloat16* __restrict__ Qhi, const __nv_bfloat16* __restrict__ Qlo,
    const __nv_bfloat16* __restrict__ Khi, const __nv_bfloat16* __restrict__ Klo,
    const __nv_bfloat16* __restrict__ Vhi, const __nv_bfloat16* __restrict__ Vlo,
    __nv_bfloat16* __restrict__ Chi, __nv_bfloat16* __restrict__ Clo)
{
    extern __shared__ char sm[];
    const uint32_t sb = smem_u32(sm);

    const int qt = blockIdx.x, h = blockIdx.y, b = blockIdx.z;
    const int tid = threadIdx.x, w = tid >> 5, lane = tid & 31;
    const float SCALE = 0.08838834764831845f;   // 1/sqrt(128)
    const float L2E = 1.4426950408889634f;

    const size_t qrow0 = (size_t)b * S_ + qt * 128;
    const size_t hcol = (size_t)h * D_;

    // ---- KV stage loader (cp.async) ----
    auto load_kv = [&](int kt, int st) {
        const size_t krow0 = (size_t)b * S_ + kt * 64;
        const uint32_t base = sb + FKV0 + st * KV_STAGE;
        #pragma unroll
        for (int it = 0; it < 4; ++it) {
            int idx = tid + it * 256;      // 0..1023
            int r = idx >> 4, s = idx & 15;
            uint32_t off = (uint32_t)(s >> 3) * 8192 +
                           SMEM_SWIZZLE_128B((uint32_t)(r * 128 + (s & 7) * 16));
            const size_t g = (krow0 + r) * E_ + hcol + s * 8;
            cpasync16(base + KV_KH + off, Khi + g);
            cpasync16(base + KV_KL + off, Klo + g);
            cpasync16(base + KV_VH + off, Vhi + g);
            cpasync16(base + KV_VL + off, Vlo + g);
        }
    };

    load_kv(0, 0); CP_COMMIT();
    load_kv(1, 1); CP_COMMIT();

    // ---- Q fill (once, regular stores) ----
    #pragma unroll
    for (int it = 0; it < 8; ++it) {
        int idx = tid + it * 256;          // 0..2047
        int r = idx >> 4, s = idx & 15;
        uint32_t off = (uint32_t)(s >> 3) * 16384 +
                       SMEM_SWIZZLE_128B((uint32_t)(r * 128 + (s & 7) * 16));
        const size_t g = (qrow0 + r) * E_ + hcol + s * 8;
        *(uint4*)(sm + FQ_H + off) = *(const uint4*)(Qhi + g);
        *(uint4*)(sm + FQ_L + off) = *(const uint4*)(Qlo + g);
    }

    float oacc[16][4];
    #pragma unroll
    for (int f = 0; f < 16; ++f)
        #pragma unroll
        for (int j = 0; j < 4; ++j) oacc[f][j] = 0.f;
    float m0 = -1e30f, m1 = -1e30f, l0 = 0.f, l1 = 0.f;

    const uint32_t aRowL = w * 16 + (lane & 15);
    const uint32_t aColL = (lane >> 4) * 8;
    const uint32_t bRowL = lane & 7;
    const uint32_t bColL = ((lane >> 3) & 1) * 8;
    const uint32_t vR = lane & 7, vM = lane >> 3;

    for (int kt = 0; kt < 32; ++kt) {
        if (kt == 31) { CP_WAIT0(); } else { CP_WAIT1(); }
        __syncthreads();
        const uint32_t kvb = sb + FKV0 + (kt & 1) * KV_STAGE;

        // ---- S = Q K^T : 16x64 per warp, 3-term ----
        float sacc[8][4];
        #pragma unroll
        for (int ni = 0; ni < 8; ++ni)
            #pragma unroll
            for (int j = 0; j < 4; ++j) sacc[ni][j] = 0.f;

        #pragma unroll
        for (int half = 0; half < 2; ++half) {
            #pragma unroll
            for (int ks = 0; ks < 4; ++ks) {
                const uint32_t kb = ks * 16;
                uint32_t ah[4], al[4];
                uint32_t aoff = SMEM_SWIZZLE_128B(aRowL * 128 + (kb + aColL) * 2);
                ldsm_x4(ah, sb + FQ_H + half * 16384 + aoff);
                ldsm_x4(al, sb + FQ_L + half * 16384 + aoff);
                #pragma unroll
                for (int ni = 0; ni < 8; ++ni) {
                    uint32_t bh[2], bl[2];
                    uint32_t boff = SMEM_SWIZZLE_128B((bRowL + ni * 8) * 128 + (kb + bColL) * 2);
                    ldsm_x2(bh, kvb + KV_KH + half * 8192 + boff);
                    ldsm_x2(bl, kvb + KV_KL + half * 8192 + boff);
                    mma16816(sacc[ni], ah, bh);
                    mma16816(sacc[ni], ah, bl);
                    mma16816(sacc[ni], al, bh);
                }
            }
        }
        #pragma unroll
        for (int ni = 0; ni < 8; ++ni)
            #pragma unroll
            for (int j = 0; j < 4; ++j) sacc[ni][j] *= SCALE;

        // ---- online softmax ----
        float mx0 = -1e30f, mx1 = -1e30f;
        #pragma unroll
        for (int ni = 0; ni < 8; ++ni) {
            mx0 = fmaxf(mx0, fmaxf(sacc[ni][0], sacc[ni][1]));
            mx1 = fmaxf(mx1, fmaxf(sacc[ni][2], sacc[ni][3]));
        }
        mx0 = fmaxf(mx0, __shfl_xor_sync(0xffffffffu, mx0, 1));
        mx0 = fmaxf(mx0, __shfl_xor_sync(0xffffffffu, mx0, 2));
        mx1 = fmaxf(mx1, __shfl_xor_sync(0xffffffffu, mx1, 1));
        mx1 = fmaxf(mx1, __shfl_xor_sync(0xffffffffu, mx1, 2));
        const float mn0 = fmaxf(m0, mx0), mn1 = fmaxf(m1, mx1);
        const float al0 = ex2f((m0 - mn0) * L2E), al1 = ex2f((m1 - mn1) * L2E);
        m0 = mn0; m1 = mn1;

        uint32_t ph[8][2], pl[8][2];
        float ls0 = 0.f, ls1 = 0.f;
        #pragma unroll
        for (int ni = 0; ni < 8; ++ni) {
            float p00 = ex2f((sacc[ni][0] - mn0) * L2E);
            float p01 = ex2f((sacc[ni][1] - mn0) * L2E);
            float p10 = ex2f((sacc[ni][2] - mn1) * L2E);
            float p11 = ex2f((sacc[ni][3] - mn1) * L2E);
            ls0 += p00 + p01;
            ls1 += p10 + p11;
            uint32_t hp0 = packbf(p00, p01);
            uint32_t hp1 = packbf(p10, p11);
            ph[ni][0] = hp0;
            ph[ni][1] = hp1;
            pl[ni][0] = packbf(p00 - lobf(hp0), p01 - hibf(hp0));
            pl[ni][1] = packbf(p10 - lobf(hp1), p11 - hibf(hp1));
        }
        ls0 += __shfl_xor_sync(0xffffffffu, ls0, 1);
        ls0 += __shfl_xor_sync(0xffffffffu, ls0, 2);
        ls1 += __shfl_xor_sync(0xffffffffu, ls1, 1);
        ls1 += __shfl_xor_sync(0xffffffffu, ls1, 2);
        l0 = l0 * al0 + ls0;
        l1 = l1 * al1 + ls1;

        #pragma unroll
        for (int f = 0; f < 16; ++f) {
            oacc[f][0] *= al0; oacc[f][1] *= al0;
            oacc[f][2] *= al1; oacc[f][3] *= al1;
        }

        // ---- O += P V : 3-term ----
        #pragma unroll
        for (int kf = 0; kf < 4; ++kf) {
            uint32_t aPh[4] = { ph[2*kf][0], ph[2*kf][1], ph[2*kf+1][0], ph[2*kf+1][1] };
            uint32_t aPl[4] = { pl[2*kf][0], pl[2*kf][1], pl[2*kf+1][0], pl[2*kf+1][1] };
            #pragma unroll
            for (int nd = 0; nd < 8; ++nd) {
                const uint32_t sub = (nd >> 2) * 8192;
                const uint32_t dd = (nd & 3) * 16;
                const uint32_t kvr = kf * 16 + (vM & 1) * 8 + vR;
                const uint32_t dc = dd + (vM >> 1) * 8;
                const uint32_t voff = SMEM_SWIZZLE_128B(kvr * 128 + dc * 2);
                uint32_t bh4[4], bl4[4];
                ldsm_x4t(bh4, kvb + KV_VH + sub + voff);
                ldsm_x4t(bl4, kvb + KV_VL + sub + voff);
                mma16816(oacc[2*nd],     aPh, bh4);
                mma16816(oacc[2*nd],     aPh, bl4);
                mma16816(oacc[2*nd],     aPl, bh4);
                mma16816(oacc[2*nd + 1], aPh, bh4 + 2);
                mma16816(oacc[2*nd + 1], aPh, bl4 + 2);
                mma16816(oacc[2*nd + 1], aPl, bh4 + 2);
            }
        }

        __syncthreads();
        if (kt + 2 < 32) { load_kv(kt + 2, kt & 1); CP_COMMIT(); }
    }

    // ---- finalize: split bf16 output ----
    const float inv0 = 1.f / l0, inv1 = 1.f / l1;
    const int rQuad = lane >> 2, cPair = (lane & 3) * 2;
    const size_t row0 = qrow0 + w * 16 + rQuad;
    #pragma unroll
    for (int f = 0; f < 16; ++f) {
        int d = f * 8 + cPair;
        float o00 = oacc[f][0] * inv0, o01 = oacc[f][1] * inv0;
        float o10 = oacc[f][2] * inv1, o11 = oacc[f][3] * inv1;
        size_t i0 = (row0 * E_ + hcol + d) >> 1;
        size_t i1 = ((row0 + 8) * E_ + hcol + d) >> 1;
        uint32_t h0 = packbf(o00, o01);
        uint32_t h1 = packbf(o10, o11);
        ((uint32_t*)Chi)[i0] = h0;
        ((uint32_t*)Chi)[i1] = h1;
        ((uint32_t*)Clo)[i0] = packbf(o00 - lobf(h0), o01 - hibf(h0));
        ((uint32_t*)Clo)[i1] = packbf(o10 - lobf(h1), o11 - hibf(h1));
    }
}

// ---------------------------------------------------------------------------
extern "C" void kernel_launch(void* const* d_in, const int* in_sizes, int n_in,
                              void* d_out, int out_size)
{
    const float* query  = (const float*)d_in[0];
    const float* key_in = (const float*)d_in[1];
    const float* value  = (const float*)d_in[2];
    const float* Wq = (const float*)d_in[3];
    const float* bq = (const float*)d_in[4];
    const float* Wk = (const float*)d_in[5];
    const float* bk = (const float*)d_in[6];
    const float* Wv = (const float*)d_in[7];
    const float* bv = (const float*)d_in[8];
    const float* Wo = (const float*)d_in[9];
    const float* bo = (const float*)d_in[10];
    float* out = (float*)d_out;

    __nv_bfloat16 *Ahi, *Alo, *Whi, *Wlo;
    __nv_bfloat16 *Qhi, *Qlo, *Khi, *Klo, *Vhi, *Vlo, *Chi, *Clo;
    cudaGetSymbolAddress((void**)&Ahi, g_Ahi);
    cudaGetSymbolAddress((void**)&Alo, g_Alo);
    cudaGetSymbolAddress((void**)&Whi, g_Whi);
    cudaGetSymbolAddress((void**)&Wlo, g_Wlo);
    cudaGetSymbolAddress((void**)&Qhi, g_Qhi);
    cudaGetSymbolAddress((void**)&Qlo, g_Qlo);
    cudaGetSymbolAddress((void**)&Khi, g_Khi);
    cudaGetSymbolAddress((void**)&Klo, g_Klo);
    cudaGetSymbolAddress((void**)&Vhi, g_Vhi);
    cudaGetSymbolAddress((void**)&Vlo, g_Vlo);
    cudaGetSymbolAddress((void**)&Chi, g_Chi);
    cudaGetSymbolAddress((void**)&Clo, g_Clo);

    cudaFuncSetAttribute(flash_mma_kernel,
                         cudaFuncAttributeMaxDynamicSharedMemorySize, FL_SMEM);
    cudaFuncSetAttribute(gemm_mma_kernel<true>,
                         cudaFuncAttributeMaxDynamicSharedMemorySize, GEMM_SMEM);
    cudaFuncSetAttribute(gemm_mma_kernel<false>,
                         cudaFuncAttributeMaxDynamicSharedMemorySize, GEMM_SMEM);

    const dim3 cw(E_ / 32, E_ / 32);
    const int  sa = (MROWS * E_ / 4) / 256;
    const dim3 gg(E_ / 128, MROWS / 128);
    const dim3 fg(S_ / 128, H_, B_);           // (16, 16, 2)

    // Q projection -> split bf16
    convW_kernel<<<cw, 256>>>(Wq, Whi, Wlo);
    splitA_kernel<<<sa, 256>>>(query, Ahi, Alo);
    gemm_mma_kernel<true><<<gg, 256, GEMM_SMEM>>>(Ahi, Alo, Whi, Wlo, bq, nullptr, Qhi, Qlo);
    // K projection -> split bf16
    convW_kernel<<<cw, 256>>>(Wk, Whi, Wlo);
    splitA_kernel<<<sa, 256>>>(key_in, Ahi, Alo);
    gemm_mma_kernel<true><<<gg, 256, GEMM_SMEM>>>(Ahi, Alo, Whi, Wlo, bk, nullptr, Khi, Klo);
    // V projection -> split bf16
    convW_kernel<<<cw, 256>>>(Wv, Whi, Wlo);
    splitA_kernel<<<sa, 256>>>(value, Ahi, Alo);
    gemm_mma_kernel<true><<<gg, 256, GEMM_SMEM>>>(Ahi, Alo, Whi, Wlo, bv, nullptr, Vhi, Vlo);
    // Attention -> split bf16 context
    flash_mma_kernel<<<fg, 256, FL_SMEM>>>(Qhi, Qlo, Khi, Klo, Vhi, Vlo, Chi, Clo);
    // Output projection -> fp32 out
    convW_kernel<<<cw, 256>>>(Wo, Whi, Wlo);
    gemm_mma_kernel<false><<<gg, 256, GEMM_SMEM>>>(Chi, Clo, Whi, Wlo, bo, out, nullptr, nullptr);
}

// round 8
// speedup vs baseline: 1.5946x; 1.4283x over previous
#include <cuda_runtime.h>
#include <cuda_bf16.h>
#include <cstdint>

// Problem constants
#define B_ 2
#define S_ 2048
#define E_ 2048
#define H_ 16
#define D_ 128
#define MROWS (B_ * S_)   // 4096

// ---------------------------------------------------------------------------
// Scratch (no cudaMalloc allowed) — all bf16 split pairs
// ---------------------------------------------------------------------------
__device__ __nv_bfloat16 g_Ahi[(size_t)MROWS * E_];
__device__ __nv_bfloat16 g_Alo[(size_t)MROWS * E_];
__device__ __nv_bfloat16 g_Whi[(size_t)E_ * E_];
__device__ __nv_bfloat16 g_Wlo[(size_t)E_ * E_];
__device__ __nv_bfloat16 g_Qhi[(size_t)MROWS * E_];
__device__ __nv_bfloat16 g_Qlo[(size_t)MROWS * E_];
__device__ __nv_bfloat16 g_Khi[(size_t)MROWS * E_];
__device__ __nv_bfloat16 g_Klo[(size_t)MROWS * E_];
__device__ __nv_bfloat16 g_Vhi[(size_t)MROWS * E_];
__device__ __nv_bfloat16 g_Vlo[(size_t)MROWS * E_];
__device__ __nv_bfloat16 g_Chi[(size_t)MROWS * E_];
__device__ __nv_bfloat16 g_Clo[(size_t)MROWS * E_];

// ---------------------------------------------------------------------------
// Helpers (legal on base sm_103 target)
// ---------------------------------------------------------------------------
__device__ __forceinline__ uint32_t smem_u32(const void* p) {
    uint32_t a;
    asm("{ .reg .u64 t; cvta.to.shared.u64 t, %1; cvt.u32.u64 %0, t; }"
        : "=r"(a) : "l"(p));
    return a;
}
__device__ __forceinline__ void ldsm_x4(uint32_t* r, uint32_t addr) {
    asm volatile("ldmatrix.sync.aligned.m8n8.x4.shared.b16 {%0,%1,%2,%3}, [%4];"
        : "=r"(r[0]), "=r"(r[1]), "=r"(r[2]), "=r"(r[3]) : "r"(addr));
}
__device__ __forceinline__ void ldsm_x2(uint32_t* r, uint32_t addr) {
    asm volatile("ldmatrix.sync.aligned.m8n8.x2.shared.b16 {%0,%1}, [%2];"
        : "=r"(r[0]), "=r"(r[1]) : "r"(addr));
}
__device__ __forceinline__ void ldsm_x4t(uint32_t* r, uint32_t addr) {
    asm volatile("ldmatrix.sync.aligned.m8n8.x4.trans.shared.b16 {%0,%1,%2,%3}, [%4];"
        : "=r"(r[0]), "=r"(r[1]), "=r"(r[2]), "=r"(r[3]) : "r"(addr));
}
__device__ __forceinline__ void mma16816(float* c, const uint32_t* a, const uint32_t* b) {
    asm volatile(
        "mma.sync.aligned.m16n8k16.row.col.f32.bf16.bf16.f32 "
        "{%0,%1,%2,%3}, {%4,%5,%6,%7}, {%8,%9}, {%0,%1,%2,%3};"
        : "+f"(c[0]), "+f"(c[1]), "+f"(c[2]), "+f"(c[3])
        : "r"(a[0]), "r"(a[1]), "r"(a[2]), "r"(a[3]), "r"(b[0]), "r"(b[1]));
}
__device__ __forceinline__ float ex2f(float x) {
    float y; asm("ex2.approx.f32 %0, %1;" : "=f"(y) : "f"(x)); return y;
}
__device__ __forceinline__ uint32_t packbf(float a, float b) {
    uint32_t r; asm("cvt.rn.bf16x2.f32 %0, %1, %2;" : "=r"(r) : "f"(b), "f"(a));
    return r;
}
__device__ __forceinline__ float lobf(uint32_t p)  { return __uint_as_float(p << 16); }
__device__ __forceinline__ float hibf(uint32_t p)  { return __uint_as_float(p & 0xffff0000u); }

__device__ __forceinline__ void split4(float4 v, uint2& hi, uint2& lo) {
    uint32_t h0 = packbf(v.x, v.y), h1 = packbf(v.z, v.w);
    hi.x = h0; hi.y = h1;
    lo.x = packbf(v.x - lobf(h0), v.y - hibf(h0));
    lo.y = packbf(v.z - lobf(h1), v.w - hibf(h1));
}

__device__ __forceinline__ void cpasync16(uint32_t saddr, const void* g) {
    asm volatile("cp.async.cg.shared.global [%0], [%1], 16;" :: "r"(saddr), "l"(g));
}
#define CP_COMMIT() asm volatile("cp.async.commit_group;" ::: "memory")
#define CP_WAIT1()  asm volatile("cp.async.wait_group 1;" ::: "memory")
#define CP_WAIT0()  asm volatile("cp.async.wait_group 0;" ::: "memory")

#define SMEM_SWIZZLE_128B(off) ((off) ^ (((off) >> 3) & 0x70))
#define SMEM_SWIZZLE_64B(off)  ((off) ^ (((off) >> 3) & 0x30))

// ---------------------------------------------------------------------------
// Split fp32 activations into (hi, lo) bf16, same layout [M][K]
// ---------------------------------------------------------------------------
__global__ void __launch_bounds__(256) splitA_kernel(
    const float* __restrict__ x, __nv_bfloat16* __restrict__ hi,
    __nv_bfloat16* __restrict__ lo)
{
    size_t i = (size_t)blockIdx.x * 256 + threadIdx.x;
    float4 v = ((const float4*)x)[i];
    uint2 h, l;
    split4(v, h, l);
    ((uint2*)hi)[i] = h;
    ((uint2*)lo)[i] = l;
}

// ---------------------------------------------------------------------------
// Transpose + split fp32 weights W[K][N] -> hi/lo bf16 [N][K]
// ---------------------------------------------------------------------------
__global__ void __launch_bounds__(256) convW_kernel(
    const float* __restrict__ W, __nv_bfloat16* __restrict__ hi,
    __nv_bfloat16* __restrict__ lo)
{
    __shared__ float t[32][33];
    int tx = threadIdx.x & 31, ty = threadIdx.x >> 5;
    int nb = blockIdx.x * 32, kb = blockIdx.y * 32;
    #pragma unroll
    for (int i = 0; i < 4; ++i) {
        int k = kb + ty + i * 8;
        t[ty + i * 8][tx] = W[(size_t)k * E_ + nb + tx];
    }
    __syncthreads();
    #pragma unroll
    for (int i = 0; i < 4; ++i) {
        int n = nb + ty + i * 8;
        float v = t[tx][ty + i * 8];
        __nv_bfloat16 h = __float2bfloat16(v);
        hi[(size_t)n * E_ + kb + tx] = h;
        lo[(size_t)n * E_ + kb + tx] = __float2bfloat16(v - __bfloat162float(h));
    }
}

// ---------------------------------------------------------------------------
// mma.sync split-bf16 GEMM, 2-stage cp.async pipeline with BK=32.
//   Stage = 4 x [128][32] bf16 SW64 tiles = 32KB; 2 stages = 64KB -> 3 CTA/SM.
//   C[M,N] = A[M,K]*B[N,K]^T + bias;  D = Ahi*Bhi + Ahi*Blo + Alo*Bhi.
// Templated epilogue: SPLIT=false -> fp32 C; SPLIT=true -> hi/lo bf16.
// ---------------------------------------------------------------------------
#define G_STAGE 32768
#define G_TILE  8192
#define GEMM_SMEM (2 * G_STAGE)
#define G_NKC 64   // K / 32

template <bool SPLIT>
__global__ void __launch_bounds__(256) gemm_mma_kernel(
    const __nv_bfloat16* __restrict__ Ahi, const __nv_bfloat16* __restrict__ Alo,
    const __nv_bfloat16* __restrict__ Bhi, const __nv_bfloat16* __restrict__ Blo,
    const float* __restrict__ bias, float* __restrict__ C,
    __nv_bfloat16* __restrict__ Chi, __nv_bfloat16* __restrict__ Clo)
{
    extern __shared__ char smc[];
    const uint32_t sb = smem_u32(smc);

    const int tid  = threadIdx.x;
    const int wid  = tid >> 5;
    const int lane = tid & 31;
    const int bx = blockIdx.x;
    const int by = blockIdx.y;

    const int warpM = (wid >> 2) * 64;
    const int warpN = (wid & 3) * 32;

    const size_t aRow0 = (size_t)by * 128;
    const size_t bRow0 = (size_t)bx * 128;

    float acc[4][4][4];
    #pragma unroll
    for (int mi = 0; mi < 4; ++mi)
        #pragma unroll
        for (int ni = 0; ni < 4; ++ni)
            #pragma unroll
            for (int j = 0; j < 4; ++j) acc[mi][ni][j] = 0.f;

    const uint32_t aRowL = warpM + (lane & 15);
    const uint32_t aColL = (lane >> 4) * 8;
    const uint32_t bRowL = warpN + (lane & 7);
    const uint32_t bColL = ((lane >> 3) & 1) * 8;

    // per-thread load coords: 512 chunks (16B) per tile, 2 per thread
    const int ldR0 = tid >> 2;       // 0..63
    const int ldS  = tid & 3;        // 16B chunk in 64B row

    auto load_stage = [&](int kc, int st) {
        const int k0 = kc * 32;
        const uint32_t base = sb + st * G_STAGE;
        #pragma unroll
        for (int it = 0; it < 2; ++it) {
            const int r = ldR0 + it * 64;
            const uint32_t o = SMEM_SWIZZLE_64B((uint32_t)(r * 64 + ldS * 16));
            const size_t gA = (aRow0 + r) * E_ + k0 + ldS * 8;
            const size_t gB = (bRow0 + r) * E_ + k0 + ldS * 8;
            cpasync16(base + o,              Ahi + gA);
            cpasync16(base + G_TILE + o,     Alo + gA);
            cpasync16(base + 2 * G_TILE + o, Bhi + gB);
            cpasync16(base + 3 * G_TILE + o, Blo + gB);
        }
    };

    load_stage(0, 0); CP_COMMIT();
    load_stage(1, 1); CP_COMMIT();

    for (int kc = 0; kc < G_NKC; ++kc) {
        if (kc == G_NKC - 1) { CP_WAIT0(); } else { CP_WAIT1(); }
        __syncthreads();

        const uint32_t SAH = sb + (kc & 1) * G_STAGE;
        const uint32_t SAL = SAH + G_TILE;
        const uint32_t SBH = SAH + 2 * G_TILE;
        const uint32_t SBL = SAH + 3 * G_TILE;

        #pragma unroll
        for (int ks = 0; ks < 2; ++ks) {
            const uint32_t kb = ks * 16;
            uint32_t ah[4][4], al[4][4], bh[4][2], bl[4][2];
            #pragma unroll
            for (int mi = 0; mi < 4; ++mi) {
                uint32_t off = (aRowL + mi * 16) * 64 + (kb + aColL) * 2;
                off = SMEM_SWIZZLE_64B(off);
                ldsm_x4(ah[mi], SAH + off);
                ldsm_x4(al[mi], SAL + off);
            }
            #pragma unroll
            for (int ni = 0; ni < 4; ++ni) {
                uint32_t off = (bRowL + ni * 8) * 64 + (kb + bColL) * 2;
                off = SMEM_SWIZZLE_64B(off);
                ldsm_x2(bh[ni], SBH + off);
                ldsm_x2(bl[ni], SBL + off);
            }
            #pragma unroll
            for (int mi = 0; mi < 4; ++mi)
                #pragma unroll
                for (int ni = 0; ni < 4; ++ni) {
                    mma16816(acc[mi][ni], ah[mi], bh[ni]);
                    mma16816(acc[mi][ni], ah[mi], bl[ni]);
                    mma16816(acc[mi][ni], al[mi], bh[ni]);
                }
        }
        __syncthreads();
        if (kc + 2 < G_NKC) { load_stage(kc + 2, kc & 1); CP_COMMIT(); }
    }

    const int rQuad = lane >> 2;
    const int cPair = (lane & 3) * 2;
    #pragma unroll
    for (int mi = 0; mi < 4; ++mi) {
        #pragma unroll
        for (int ni = 0; ni < 4; ++ni) {
            int row = by * 128 + warpM + mi * 16 + rQuad;
            int col = bx * 128 + warpN + ni * 8 + cPair;
            float b0 = bias[col], b1 = bias[col + 1];
            float o00 = acc[mi][ni][0] + b0, o01 = acc[mi][ni][1] + b1;
            float o10 = acc[mi][ni][2] + b0, o11 = acc[mi][ni][3] + b1;
            if constexpr (SPLIT) {
                size_t i0 = ((size_t)row * E_ + col) >> 1;
                size_t i1 = ((size_t)(row + 8) * E_ + col) >> 1;
                uint32_t h0 = packbf(o00, o01);
                uint32_t h1 = packbf(o10, o11);
                ((uint32_t*)Chi)[i0] = h0;
                ((uint32_t*)Chi)[i1] = h1;
                ((uint32_t*)Clo)[i0] = packbf(o00 - lobf(h0), o01 - hibf(h0));
                ((uint32_t*)Clo)[i1] = packbf(o10 - lobf(h1), o11 - hibf(h1));
            } else {
                *(float2*)(C + (size_t)row * E_ + col)       = make_float2(o00, o01);
                *(float2*)(C + (size_t)(row + 8) * E_ + col) = make_float2(o10, o11);
            }
        }
    }
}

// ---------------------------------------------------------------------------
// Tensor-core flash attention, BM=128 (8 warps), pre-split bf16 inputs,
// 2-stage cp.async KV pipeline, split bf16 output.  (unchanged from R7)
// ---------------------------------------------------------------------------
#define FQ_H   0
#define FQ_L   32768
#define FKV0   65536
#define KV_STAGE 65536
#define KV_KH  0
#define KV_KL  16384
#define KV_VH  32768
#define KV_VL  49152
#define FL_SMEM 196608

__global__ void __launch_bounds__(256) flash_mma_kernel(
    const __nv_bfloat16* __restrict__ Qhi, const __nv_bfloat16* __restrict__ Qlo,
    const __nv_bfloat16* __restrict__ Khi, const __nv_bfloat16* __restrict__ Klo,
    const __nv_bfloat16* __restrict__ Vhi, const __nv_bfloat16* __restrict__ Vlo,
    __nv_bfloat16* __restrict__ Chi, __nv_bfloat16* __restrict__ Clo)
{
    extern __shared__ char sm[];
    const uint32_t sb = smem_u32(sm);

    const int qt = blockIdx.x, h = blockIdx.y, b = blockIdx.z;
    const int tid = threadIdx.x, w = tid >> 5, lane = tid & 31;
    const float SCALE = 0.08838834764831845f;
    const float L2E = 1.4426950408889634f;

    const size_t qrow0 = (size_t)b * S_ + qt * 128;
    const size_t hcol = (size_t)h * D_;

    auto load_kv = [&](int kt, int st) {
        const size_t krow0 = (size_t)b * S_ + kt * 64;
        const uint32_t base = sb + FKV0 + st * KV_STAGE;
        #pragma unroll
        for (int it = 0; it < 4; ++it) {
            int idx = tid + it * 256;
            int r = idx >> 4, s = idx & 15;
            uint32_t off = (uint32_t)(s >> 3) * 8192 +
                           SMEM_SWIZZLE_128B((uint32_t)(r * 128 + (s & 7) * 16));
            const size_t g = (krow0 + r) * E_ + hcol + s * 8;
            cpasync16(base + KV_KH + off, Khi + g);
            cpasync16(base + KV_KL + off, Klo + g);
            cpasync16(base + KV_VH + off, Vhi + g);
            cpasync16(base + KV_VL + off, Vlo + g);
        }
    };

    load_kv(0, 0); CP_COMMIT();
    load_kv(1, 1); CP_COMMIT();

    #pragma unroll
    for (int it = 0; it < 8; ++it) {
        int idx = tid + it * 256;
        int r = idx >> 4, s = idx & 15;
        uint32_t off = (uint32_t)(s >> 3) * 16384 +
                       SMEM_SWIZZLE_128B((uint32_t)(r * 128 + (s & 7) * 16));
        const size_t g = (qrow0 + r) * E_ + hcol + s * 8;
        *(uint4*)(sm + FQ_H + off) = *(const uint4*)(Qhi + g);
        *(uint4*)(sm + FQ_L + off) = *(const uint4*)(Qlo + g);
    }

    float oacc[16][4];
    #pragma unroll
    for (int f = 0; f < 16; ++f)
        #pragma unroll
        for (int j = 0; j < 4; ++j) oacc[f][j] = 0.f;
    float m0 = -1e30f, m1 = -1e30f, l0 = 0.f, l1 = 0.f;

    const uint32_t aRowL = w * 16 + (lane & 15);
    const uint32_t aColL = (lane >> 4) * 8;
    const uint32_t bRowL = lane & 7;
    const uint32_t bColL = ((lane >> 3) & 1) * 8;
    const uint32_t vR = lane & 7, vM = lane >> 3;

    for (int kt = 0; kt < 32; ++kt) {
        if (kt == 31) { CP_WAIT0(); } else { CP_WAIT1(); }
        __syncthreads();
        const uint32_t kvb = sb + FKV0 + (kt & 1) * KV_STAGE;

        float sacc[8][4];
        #pragma unroll
        for (int ni = 0; ni < 8; ++ni)
            #pragma unroll
            for (int j = 0; j < 4; ++j) sacc[ni][j] = 0.f;

        #pragma unroll
        for (int half = 0; half < 2; ++half) {
            #pragma unroll
            for (int ks = 0; ks < 4; ++ks) {
                const uint32_t kb = ks * 16;
                uint32_t ah[4], al[4];
                uint32_t aoff = SMEM_SWIZZLE_128B(aRowL * 128 + (kb + aColL) * 2);
                ldsm_x4(ah, sb + FQ_H + half * 16384 + aoff);
                ldsm_x4(al, sb + FQ_L + half * 16384 + aoff);
                #pragma unroll
                for (int ni = 0; ni < 8; ++ni) {
                    uint32_t bh[2], bl[2];
                    uint32_t boff = SMEM_SWIZZLE_128B((bRowL + ni * 8) * 128 + (kb + bColL) * 2);
                    ldsm_x2(bh, kvb + KV_KH + half * 8192 + boff);
                    ldsm_x2(bl, kvb + KV_KL + half * 8192 + boff);
                    mma16816(sacc[ni], ah, bh);
                    mma16816(sacc[ni], ah, bl);
                    mma16816(sacc[ni], al, bh);
                }
            }
        }
        #pragma unroll
        for (int ni = 0; ni < 8; ++ni)
            #pragma unroll
            for (int j = 0; j < 4; ++j) sacc[ni][j] *= SCALE;

        float mx0 = -1e30f, mx1 = -1e30f;
        #pragma unroll
        for (int ni = 0; ni < 8; ++ni) {
            mx0 = fmaxf(mx0, fmaxf(sacc[ni][0], sacc[ni][1]));
            mx1 = fmaxf(mx1, fmaxf(sacc[ni][2], sacc[ni][3]));
        }
        mx0 = fmaxf(mx0, __shfl_xor_sync(0xffffffffu, mx0, 1));
        mx0 = fmaxf(mx0, __shfl_xor_sync(0xffffffffu, mx0, 2));
        mx1 = fmaxf(mx1, __shfl_xor_sync(0xffffffffu, mx1, 1));
        mx1 = fmaxf(mx1, __shfl_xor_sync(0xffffffffu, mx1, 2));
        const float mn0 = fmaxf(m0, mx0), mn1 = fmaxf(m1, mx1);
        const float al0 = ex2f((m0 - mn0) * L2E), al1 = ex2f((m1 - mn1) * L2E);
        m0 = mn0; m1 = mn1;

        uint32_t ph[8][2], pl[8][2];
        float ls0 = 0.f, ls1 = 0.f;
        #pragma unroll
        for (int ni = 0; ni < 8; ++ni) {
            float p00 = ex2f((sacc[ni][0] - mn0) * L2E);
            float p01 = ex2f((sacc[ni][1] - mn0) * L2E);
            float p10 = ex2f((sacc[ni][2] - mn1) * L2E);
            float p11 = ex2f((sacc[ni][3] - mn1) * L2E);
            ls0 += p00 + p01;
            ls1 += p10 + p11;
            uint32_t hp0 = packbf(p00, p01);
            uint32_t hp1 = packbf(p10, p11);
            ph[ni][0] = hp0;
            ph[ni][1] = hp1;
            pl[ni][0] = packbf(p00 - lobf(hp0), p01 - hibf(hp0));
            pl[ni][1] = packbf(p10 - lobf(hp1), p11 - hibf(hp1));
        }
        ls0 += __shfl_xor_sync(0xffffffffu, ls0, 1);
        ls0 += __shfl_xor_sync(0xffffffffu, ls0, 2);
        ls1 += __shfl_xor_sync(0xffffffffu, ls1, 1);
        ls1 += __shfl_xor_sync(0xffffffffu, ls1, 2);
        l0 = l0 * al0 + ls0;
        l1 = l1 * al1 + ls1;

        #pragma unroll
        for (int f = 0; f < 16; ++f) {
            oacc[f][0] *= al0; oacc[f][1] *= al0;
            oacc[f][2] *= al1; oacc[f][3] *= al1;
        }

        #pragma unroll
        for (int kf = 0; kf < 4; ++kf) {
            uint32_t aPh[4] = { ph[2*kf][0], ph[2*kf][1], ph[2*kf+1][0], ph[2*kf+1][1] };
            uint32_t aPl[4] = { pl[2*kf][0], pl[2*kf][1], pl[2*kf+1][0], pl[2*kf+1][1] };
            #pragma unroll
            for (int nd = 0; nd < 8; ++nd) {
                const uint32_t sub = (nd >> 2) * 8192;
                const uint32_t dd = (nd & 3) * 16;
                const uint32_t kvr = kf * 16 + (vM & 1) * 8 + vR;
                const uint32_t dc = dd + (vM >> 1) * 8;
                const uint32_t voff = SMEM_SWIZZLE_128B(kvr * 128 + dc * 2);
                uint32_t bh4[4], bl4[4];
                ldsm_x4t(bh4, kvb + KV_VH + sub + voff);
                ldsm_x4t(bl4, kvb + KV_VL + sub + voff);
                mma16816(oacc[2*nd],     aPh, bh4);
                mma16816(oacc[2*nd],     aPh, bl4);
                mma16816(oacc[2*nd],     aPl, bh4);
                mma16816(oacc[2*nd + 1], aPh, bh4 + 2);
                mma16816(oacc[2*nd + 1], aPh, bl4 + 2);
                mma16816(oacc[2*nd + 1], aPl, bh4 + 2);
            }
        }

        __syncthreads();
        if (kt + 2 < 32) { load_kv(kt + 2, kt & 1); CP_COMMIT(); }
    }

    const float inv0 = 1.f / l0, inv1 = 1.f / l1;
    const int rQuad = lane >> 2, cPair = (lane & 3) * 2;
    const size_t row0 = qrow0 + w * 16 + rQuad;
    #pragma unroll
    for (int f = 0; f < 16; ++f) {
        int d = f * 8 + cPair;
        float o00 = oacc[f][0] * inv0, o01 = oacc[f][1] * inv0;
        float o10 = oacc[f][2] * inv1, o11 = oacc[f][3] * inv1;
        size_t i0 = (row0 * E_ + hcol + d) >> 1;
        size_t i1 = ((row0 + 8) * E_ + hcol + d) >> 1;
        uint32_t h0 = packbf(o00, o01);
        uint32_t h1 = packbf(o10, o11);
        ((uint32_t*)Chi)[i0] = h0;
        ((uint32_t*)Chi)[i1] = h1;
        ((uint32_t*)Clo)[i0] = packbf(o00 - lobf(h0), o01 - hibf(h0));
        ((uint32_t*)Clo)[i1] = packbf(o10 - lobf(h1), o11 - hibf(h1));
    }
}

// ---------------------------------------------------------------------------
extern "C" void kernel_launch(void* const* d_in, const int* in_sizes, int n_in,
                              void* d_out, int out_size)
{
    const float* query  = (const float*)d_in[0];
    const float* key_in = (const float*)d_in[1];
    const float* value  = (const float*)d_in[2];
    const float* Wq = (const float*)d_in[3];
    const float* bq = (const float*)d_in[4];
    const float* Wk = (const float*)d_in[5];
    const float* bk = (const float*)d_in[6];
    const float* Wv = (const float*)d_in[7];
    const float* bv = (const float*)d_in[8];
    const float* Wo = (const float*)d_in[9];
    const float* bo = (const float*)d_in[10];
    float* out = (float*)d_out;

    __nv_bfloat16 *Ahi, *Alo, *Whi, *Wlo;
    __nv_bfloat16 *Qhi, *Qlo, *Khi, *Klo, *Vhi, *Vlo, *Chi, *Clo;
    cudaGetSymbolAddress((void**)&Ahi, g_Ahi);
    cudaGetSymbolAddress((void**)&Alo, g_Alo);
    cudaGetSymbolAddress((void**)&Whi, g_Whi);
    cudaGetSymbolAddress((void**)&Wlo, g_Wlo);
    cudaGetSymbolAddress((void**)&Qhi, g_Qhi);
    cudaGetSymbolAddress((void**)&Qlo, g_Qlo);
    cudaGetSymbolAddress((void**)&Khi, g_Khi);
    cudaGetSymbolAddress((void**)&Klo, g_Klo);
    cudaGetSymbolAddress((void**)&Vhi, g_Vhi);
    cudaGetSymbolAddress((void**)&Vlo, g_Vlo);
    cudaGetSymbolAddress((void**)&Chi, g_Chi);
    cudaGetSymbolAddress((void**)&Clo, g_Clo);

    cudaFuncSetAttribute(flash_mma_kernel,
                         cudaFuncAttributeMaxDynamicSharedMemorySize, FL_SMEM);
    cudaFuncSetAttribute(gemm_mma_kernel<true>,
                         cudaFuncAttributeMaxDynamicSharedMemorySize, GEMM_SMEM);
    cudaFuncSetAttribute(gemm_mma_kernel<false>,
                         cudaFuncAttributeMaxDynamicSharedMemorySize, GEMM_SMEM);

    const dim3 cw(E_ / 32, E_ / 32);
    const int  sa = (MROWS * E_ / 4) / 256;
    const dim3 gg(E_ / 128, MROWS / 128);
    const dim3 fg(S_ / 128, H_, B_);

    // Q projection -> split bf16
    convW_kernel<<<cw, 256>>>(Wq, Whi, Wlo);
    splitA_kernel<<<sa, 256>>>(query, Ahi, Alo);
    gemm_mma_kernel<true><<<gg, 256, GEMM_SMEM>>>(Ahi, Alo, Whi, Wlo, bq, nullptr, Qhi, Qlo);
    // K projection -> split bf16
    convW_kernel<<<cw, 256>>>(Wk, Whi, Wlo);
    splitA_kernel<<<sa, 256>>>(key_in, Ahi, Alo);
    gemm_mma_kernel<true><<<gg, 256, GEMM_SMEM>>>(Ahi, Alo, Whi, Wlo, bk, nullptr, Khi, Klo);
    // V projection -> split bf16
    convW_kernel<<<cw, 256>>>(Wv, Whi, Wlo);
    splitA_kernel<<<sa, 256>>>(value, Ahi, Alo);
    gemm_mma_kernel<true><<<gg, 256, GEMM_SMEM>>>(Ahi, Alo, Whi, Wlo, bv, nullptr, Vhi, Vlo);
    // Attention -> split bf16 context
    flash_mma_kernel<<<fg, 256, FL_SMEM>>>(Qhi, Qlo, Khi, Klo, Vhi, Vlo, Chi, Clo);
    // Output projection -> fp32 out
    convW_kernel<<<cw, 256>>>(Wo, Whi, Wlo);
    gemm_mma_kernel<false><<<gg, 256, GEMM_SMEM>>>(Chi, Clo, Whi, Wlo, bo, out, nullptr, nullptr);
}

// round 9
// speedup vs baseline: 1.8205x; 1.1417x over previous
#include <cuda_runtime.h>
#include <cuda_bf16.h>
#include <cstdint>

// Problem constants
#define B_ 2
#define S_ 2048
#define E_ 2048
#define H_ 16
#define D_ 128
#define MROWS (B_ * S_)   // 4096
#define ME ((size_t)MROWS * E_)
#define EE ((size_t)E_ * E_)

// ---------------------------------------------------------------------------
// Scratch (no cudaMalloc allowed) — packed per-projection buffers
// ---------------------------------------------------------------------------
__device__ __nv_bfloat16 g_Ahi[3 * ME];   // split activations: query,key,value
__device__ __nv_bfloat16 g_Alo[3 * ME];
__device__ __nv_bfloat16 g_Whi[4 * EE];   // split transposed weights: q,k,v,o
__device__ __nv_bfloat16 g_Wlo[4 * EE];
__device__ __nv_bfloat16 g_Phi[3 * ME];   // projected Q,K,V (split)
__device__ __nv_bfloat16 g_Plo[3 * ME];
__device__ __nv_bfloat16 g_Chi[ME];       // attention context (split)
__device__ __nv_bfloat16 g_Clo[ME];

// ---------------------------------------------------------------------------
// Helpers (legal on base sm_103 target)
// ---------------------------------------------------------------------------
__device__ __forceinline__ uint32_t smem_u32(const void* p) {
    uint32_t a;
    asm("{ .reg .u64 t; cvta.to.shared.u64 t, %1; cvt.u32.u64 %0, t; }"
        : "=r"(a) : "l"(p));
    return a;
}
__device__ __forceinline__ void ldsm_x4(uint32_t* r, uint32_t addr) {
    asm volatile("ldmatrix.sync.aligned.m8n8.x4.shared.b16 {%0,%1,%2,%3}, [%4];"
        : "=r"(r[0]), "=r"(r[1]), "=r"(r[2]), "=r"(r[3]) : "r"(addr));
}
__device__ __forceinline__ void ldsm_x2(uint32_t* r, uint32_t addr) {
    asm volatile("ldmatrix.sync.aligned.m8n8.x2.shared.b16 {%0,%1}, [%2];"
        : "=r"(r[0]), "=r"(r[1]) : "r"(addr));
}
__device__ __forceinline__ void ldsm_x4t(uint32_t* r, uint32_t addr) {
    asm volatile("ldmatrix.sync.aligned.m8n8.x4.trans.shared.b16 {%0,%1,%2,%3}, [%4];"
        : "=r"(r[0]), "=r"(r[1]), "=r"(r[2]), "=r"(r[3]) : "r"(addr));
}
__device__ __forceinline__ void mma16816(float* c, const uint32_t* a, const uint32_t* b) {
    asm volatile(
        "mma.sync.aligned.m16n8k16.row.col.f32.bf16.bf16.f32 "
        "{%0,%1,%2,%3}, {%4,%5,%6,%7}, {%8,%9}, {%0,%1,%2,%3};"
        : "+f"(c[0]), "+f"(c[1]), "+f"(c[2]), "+f"(c[3])
        : "r"(a[0]), "r"(a[1]), "r"(a[2]), "r"(a[3]), "r"(b[0]), "r"(b[1]));
}
__device__ __forceinline__ float ex2f(float x) {
    float y; asm("ex2.approx.f32 %0, %1;" : "=f"(y) : "f"(x)); return y;
}
__device__ __forceinline__ uint32_t packbf(float a, float b) {
    uint32_t r; asm("cvt.rn.bf16x2.f32 %0, %1, %2;" : "=r"(r) : "f"(b), "f"(a));
    return r;
}
__device__ __forceinline__ float lobf(uint32_t p)  { return __uint_as_float(p << 16); }
__device__ __forceinline__ float hibf(uint32_t p)  { return __uint_as_float(p & 0xffff0000u); }

__device__ __forceinline__ void split4(float4 v, uint2& hi, uint2& lo) {
    uint32_t h0 = packbf(v.x, v.y), h1 = packbf(v.z, v.w);
    hi.x = h0; hi.y = h1;
    lo.x = packbf(v.x - lobf(h0), v.y - hibf(h0));
    lo.y = packbf(v.z - lobf(h1), v.w - hibf(h1));
}

__device__ __forceinline__ void cpasync16(uint32_t saddr, const void* g) {
    asm volatile("cp.async.cg.shared.global [%0], [%1], 16;" :: "r"(saddr), "l"(g));
}
#define CP_COMMIT() asm volatile("cp.async.commit_group;" ::: "memory")
#define CP_WAIT1()  asm volatile("cp.async.wait_group 1;" ::: "memory")
#define CP_WAIT0()  asm volatile("cp.async.wait_group 0;" ::: "memory")

#define SMEM_SWIZZLE_128B(off) ((off) ^ (((off) >> 3) & 0x70))
#define SMEM_SWIZZLE_64B(off)  ((off) ^ (((off) >> 3) & 0x30))

// ---------------------------------------------------------------------------
// Split fp32 activations into (hi, lo) bf16, same layout [M][K]
// ---------------------------------------------------------------------------
__global__ void __launch_bounds__(256) splitA_kernel(
    const float* __restrict__ x, __nv_bfloat16* __restrict__ hi,
    __nv_bfloat16* __restrict__ lo)
{
    size_t i = (size_t)blockIdx.x * 256 + threadIdx.x;
    float4 v = ((const float4*)x)[i];
    uint2 h, l;
    split4(v, h, l);
    ((uint2*)hi)[i] = h;
    ((uint2*)lo)[i] = l;
}

// ---------------------------------------------------------------------------
// Transpose + split fp32 weights W[K][N] -> hi/lo bf16 [N][K]
// ---------------------------------------------------------------------------
__global__ void __launch_bounds__(256) convW_kernel(
    const float* __restrict__ W, __nv_bfloat16* __restrict__ hi,
    __nv_bfloat16* __restrict__ lo)
{
    __shared__ float t[32][33];
    int tx = threadIdx.x & 31, ty = threadIdx.x >> 5;
    int nb = blockIdx.x * 32, kb = blockIdx.y * 32;
    #pragma unroll
    for (int i = 0; i < 4; ++i) {
        int k = kb + ty + i * 8;
        t[ty + i * 8][tx] = W[(size_t)k * E_ + nb + tx];
    }
    __syncthreads();
    #pragma unroll
    for (int i = 0; i < 4; ++i) {
        int n = nb + ty + i * 8;
        float v = t[tx][ty + i * 8];
        __nv_bfloat16 h = __float2bfloat16(v);
        hi[(size_t)n * E_ + kb + tx] = h;
        lo[(size_t)n * E_ + kb + tx] = __float2bfloat16(v - __bfloat162float(h));
    }
}

// ---------------------------------------------------------------------------
// mma.sync split-bf16 GEMM core (BK=32, 2-stage cp.async, 64KB smem).
// ---------------------------------------------------------------------------
#define G_STAGE 32768
#define G_TILE  8192
#define GEMM_SMEM (2 * G_STAGE)
#define G_NKC 64   // K / 32

template <bool SPLIT>
__device__ __forceinline__ void gemm_body(
    const __nv_bfloat16* __restrict__ Ahi, const __nv_bfloat16* __restrict__ Alo,
    const __nv_bfloat16* __restrict__ Bhi, const __nv_bfloat16* __restrict__ Blo,
    const float* __restrict__ bias, float* __restrict__ C,
    __nv_bfloat16* __restrict__ Chi, __nv_bfloat16* __restrict__ Clo,
    char* smc, int bx, int by)
{
    const uint32_t sb = smem_u32(smc);
    const int tid  = threadIdx.x;
    const int wid  = tid >> 5;
    const int lane = tid & 31;

    const int warpM = (wid >> 2) * 64;
    const int warpN = (wid & 3) * 32;

    const size_t aRow0 = (size_t)by * 128;
    const size_t bRow0 = (size_t)bx * 128;

    float acc[4][4][4];
    #pragma unroll
    for (int mi = 0; mi < 4; ++mi)
        #pragma unroll
        for (int ni = 0; ni < 4; ++ni)
            #pragma unroll
            for (int j = 0; j < 4; ++j) acc[mi][ni][j] = 0.f;

    const uint32_t aRowL = warpM + (lane & 15);
    const uint32_t aColL = (lane >> 4) * 8;
    const uint32_t bRowL = warpN + (lane & 7);
    const uint32_t bColL = ((lane >> 3) & 1) * 8;

    const int ldR0 = tid >> 2;
    const int ldS  = tid & 3;

    auto load_stage = [&](int kc, int st) {
        const int k0 = kc * 32;
        const uint32_t base = sb + st * G_STAGE;
        #pragma unroll
        for (int it = 0; it < 2; ++it) {
            const int r = ldR0 + it * 64;
            const uint32_t o = SMEM_SWIZZLE_64B((uint32_t)(r * 64 + ldS * 16));
            const size_t gA = (aRow0 + r) * E_ + k0 + ldS * 8;
            const size_t gB = (bRow0 + r) * E_ + k0 + ldS * 8;
            cpasync16(base + o,              Ahi + gA);
            cpasync16(base + G_TILE + o,     Alo + gA);
            cpasync16(base + 2 * G_TILE + o, Bhi + gB);
            cpasync16(base + 3 * G_TILE + o, Blo + gB);
        }
    };

    load_stage(0, 0); CP_COMMIT();
    load_stage(1, 1); CP_COMMIT();

    for (int kc = 0; kc < G_NKC; ++kc) {
        if (kc == G_NKC - 1) { CP_WAIT0(); } else { CP_WAIT1(); }
        __syncthreads();

        const uint32_t SAH = sb + (kc & 1) * G_STAGE;
        const uint32_t SAL = SAH + G_TILE;
        const uint32_t SBH = SAH + 2 * G_TILE;
        const uint32_t SBL = SAH + 3 * G_TILE;

        #pragma unroll
        for (int ks = 0; ks < 2; ++ks) {
            const uint32_t kb = ks * 16;
            uint32_t ah[4][4], al[4][4], bh[4][2], bl[4][2];
            #pragma unroll
            for (int mi = 0; mi < 4; ++mi) {
                uint32_t off = (aRowL + mi * 16) * 64 + (kb + aColL) * 2;
                off = SMEM_SWIZZLE_64B(off);
                ldsm_x4(ah[mi], SAH + off);
                ldsm_x4(al[mi], SAL + off);
            }
            #pragma unroll
            for (int ni = 0; ni < 4; ++ni) {
                uint32_t off = (bRowL + ni * 8) * 64 + (kb + bColL) * 2;
                off = SMEM_SWIZZLE_64B(off);
                ldsm_x2(bh[ni], SBH + off);
                ldsm_x2(bl[ni], SBL + off);
            }
            #pragma unroll
            for (int mi = 0; mi < 4; ++mi)
                #pragma unroll
                for (int ni = 0; ni < 4; ++ni) {
                    mma16816(acc[mi][ni], ah[mi], bh[ni]);
                    mma16816(acc[mi][ni], ah[mi], bl[ni]);
                    mma16816(acc[mi][ni], al[mi], bh[ni]);
                }
        }
        __syncthreads();
        if (kc + 2 < G_NKC) { load_stage(kc + 2, kc & 1); CP_COMMIT(); }
    }

    const int rQuad = lane >> 2;
    const int cPair = (lane & 3) * 2;
    #pragma unroll
    for (int mi = 0; mi < 4; ++mi) {
        #pragma unroll
        for (int ni = 0; ni < 4; ++ni) {
            int row = by * 128 + warpM + mi * 16 + rQuad;
            int col = bx * 128 + warpN + ni * 8 + cPair;
            float b0 = bias[col], b1 = bias[col + 1];
            float o00 = acc[mi][ni][0] + b0, o01 = acc[mi][ni][1] + b1;
            float o10 = acc[mi][ni][2] + b0, o11 = acc[mi][ni][3] + b1;
            if constexpr (SPLIT) {
                size_t i0 = ((size_t)row * E_ + col) >> 1;
                size_t i1 = ((size_t)(row + 8) * E_ + col) >> 1;
                uint32_t h0 = packbf(o00, o01);
                uint32_t h1 = packbf(o10, o11);
                ((uint32_t*)Chi)[i0] = h0;
                ((uint32_t*)Chi)[i1] = h1;
                ((uint32_t*)Clo)[i0] = packbf(o00 - lobf(h0), o01 - hibf(h0));
                ((uint32_t*)Clo)[i1] = packbf(o10 - lobf(h1), o11 - hibf(h1));
            } else {
                *(float2*)(C + (size_t)row * E_ + col)       = make_float2(o00, o01);
                *(float2*)(C + (size_t)(row + 8) * E_ + col) = make_float2(o10, o11);
            }
        }
    }
}

// Batched projection GEMM: blockIdx.z = projection (0=Q,1=K,2=V)
__global__ void __launch_bounds__(256) gemm_proj3_kernel(
    const __nv_bfloat16* __restrict__ AhiAll, const __nv_bfloat16* __restrict__ AloAll,
    const __nv_bfloat16* __restrict__ WhiAll, const __nv_bfloat16* __restrict__ WloAll,
    const float* __restrict__ b0, const float* __restrict__ b1,
    const float* __restrict__ b2,
    __nv_bfloat16* __restrict__ PhiAll, __nv_bfloat16* __restrict__ PloAll)
{
    extern __shared__ char smc[];
    const int p = blockIdx.z;
    const float* bias = (p == 0) ? b0 : (p == 1) ? b1 : b2;
    gemm_body<true>(AhiAll + p * ME, AloAll + p * ME,
                    WhiAll + p * EE, WloAll + p * EE,
                    bias, nullptr,
                    PhiAll + p * ME, PloAll + p * ME,
                    smc, blockIdx.x, blockIdx.y);
}

// Single GEMM (fp32 out) for the final projection
__global__ void __launch_bounds__(256) gemm_out_kernel(
    const __nv_bfloat16* __restrict__ Ahi, const __nv_bfloat16* __restrict__ Alo,
    const __nv_bfloat16* __restrict__ Bhi, const __nv_bfloat16* __restrict__ Blo,
    const float* __restrict__ bias, float* __restrict__ C)
{
    extern __shared__ char smc[];
    gemm_body<false>(Ahi, Alo, Bhi, Blo, bias, C, nullptr, nullptr,
                     smc, blockIdx.x, blockIdx.y);
}

// ---------------------------------------------------------------------------
// Tensor-core flash attention (unchanged from R8)
// ---------------------------------------------------------------------------
#define FQ_H   0
#define FQ_L   32768
#define FKV0   65536
#define KV_STAGE 65536
#define KV_KH  0
#define KV_KL  16384
#define KV_VH  32768
#define KV_VL  49152
#define FL_SMEM 196608

__global__ void __launch_bounds__(256) flash_mma_kernel(
    const __nv_bfloat16* __restrict__ Qhi, const __nv_bfloat16* __restrict__ Qlo,
    const __nv_bfloat16* __restrict__ Khi, const __nv_bfloat16* __restrict__ Klo,
    const __nv_bfloat16* __restrict__ Vhi, const __nv_bfloat16* __restrict__ Vlo,
    __nv_bfloat16* __restrict__ Chi, __nv_bfloat16* __restrict__ Clo)
{
    extern __shared__ char sm[];
    const uint32_t sb = smem_u32(sm);

    const int qt = blockIdx.x, h = blockIdx.y, b = blockIdx.z;
    const int tid = threadIdx.x, w = tid >> 5, lane = tid & 31;
    const float SCALE = 0.08838834764831845f;
    const float L2E = 1.4426950408889634f;

    const size_t qrow0 = (size_t)b * S_ + qt * 128;
    const size_t hcol = (size_t)h * D_;

    auto load_kv = [&](int kt, int st) {
        const size_t krow0 = (size_t)b * S_ + kt * 64;
        const uint32_t base = sb + FKV0 + st * KV_STAGE;
        #pragma unroll
        for (int it = 0; it < 4; ++it) {
            int idx = tid + it * 256;
            int r = idx >> 4, s = idx & 15;
            uint32_t off = (uint32_t)(s >> 3) * 8192 +
                           SMEM_SWIZZLE_128B((uint32_t)(r * 128 + (s & 7) * 16));
            const size_t g = (krow0 + r) * E_ + hcol + s * 8;
            cpasync16(base + KV_KH + off, Khi + g);
            cpasync16(base + KV_KL + off, Klo + g);
            cpasync16(base + KV_VH + off, Vhi + g);
            cpasync16(base + KV_VL + off, Vlo + g);
        }
    };

    load_kv(0, 0); CP_COMMIT();
    load_kv(1, 1); CP_COMMIT();

    #pragma unroll
    for (int it = 0; it < 8; ++it) {
        int idx = tid + it * 256;
        int r = idx >> 4, s = idx & 15;
        uint32_t off = (uint32_t)(s >> 3) * 16384 +
                       SMEM_SWIZZLE_128B((uint32_t)(r * 128 + (s & 7) * 16));
        const size_t g = (qrow0 + r) * E_ + hcol + s * 8;
        *(uint4*)(sm + FQ_H + off) = *(const uint4*)(Qhi + g);
        *(uint4*)(sm + FQ_L + off) = *(const uint4*)(Qlo + g);
    }

    float oacc[16][4];
    #pragma unroll
    for (int f = 0; f < 16; ++f)
        #pragma unroll
        for (int j = 0; j < 4; ++j) oacc[f][j] = 0.f;
    float m0 = -1e30f, m1 = -1e30f, l0 = 0.f, l1 = 0.f;

    const uint32_t aRowL = w * 16 + (lane & 15);
    const uint32_t aColL = (lane >> 4) * 8;
    const uint32_t bRowL = lane & 7;
    const uint32_t bColL = ((lane >> 3) & 1) * 8;
    const uint32_t vR = lane & 7, vM = lane >> 3;

    for (int kt = 0; kt < 32; ++kt) {
        if (kt == 31) { CP_WAIT0(); } else { CP_WAIT1(); }
        __syncthreads();
        const uint32_t kvb = sb + FKV0 + (kt & 1) * KV_STAGE;

        float sacc[8][4];
        #pragma unroll
        for (int ni = 0; ni < 8; ++ni)
            #pragma unroll
            for (int j = 0; j < 4; ++j) sacc[ni][j] = 0.f;

        #pragma unroll
        for (int half = 0; half < 2; ++half) {
            #pragma unroll
            for (int ks = 0; ks < 4; ++ks) {
                const uint32_t kb = ks * 16;
                uint32_t ah[4], al[4];
                uint32_t aoff = SMEM_SWIZZLE_128B(aRowL * 128 + (kb + aColL) * 2);
                ldsm_x4(ah, sb + FQ_H + half * 16384 + aoff);
                ldsm_x4(al, sb + FQ_L + half * 16384 + aoff);
                #pragma unroll
                for (int ni = 0; ni < 8; ++ni) {
                    uint32_t bh[2], bl[2];
                    uint32_t boff = SMEM_SWIZZLE_128B((bRowL + ni * 8) * 128 + (kb + bColL) * 2);
                    ldsm_x2(bh, kvb + KV_KH + half * 8192 + boff);
                    ldsm_x2(bl, kvb + KV_KL + half * 8192 + boff);
                    mma16816(sacc[ni], ah, bh);
                    mma16816(sacc[ni], ah, bl);
                    mma16816(sacc[ni], al, bh);
                }
            }
        }
        #pragma unroll
        for (int ni = 0; ni < 8; ++ni)
            #pragma unroll
            for (int j = 0; j < 4; ++j) sacc[ni][j] *= SCALE;

        float mx0 = -1e30f, mx1 = -1e30f;
        #pragma unroll
        for (int ni = 0; ni < 8; ++ni) {
            mx0 = fmaxf(mx0, fmaxf(sacc[ni][0], sacc[ni][1]));
            mx1 = fmaxf(mx1, fmaxf(sacc[ni][2], sacc[ni][3]));
        }
        mx0 = fmaxf(mx0, __shfl_xor_sync(0xffffffffu, mx0, 1));
        mx0 = fmaxf(mx0, __shfl_xor_sync(0xffffffffu, mx0, 2));
        mx1 = fmaxf(mx1, __shfl_xor_sync(0xffffffffu, mx1, 1));
        mx1 = fmaxf(mx1, __shfl_xor_sync(0xffffffffu, mx1, 2));
        const float mn0 = fmaxf(m0, mx0), mn1 = fmaxf(m1, mx1);
        const float al0 = ex2f((m0 - mn0) * L2E), al1 = ex2f((m1 - mn1) * L2E);
        m0 = mn0; m1 = mn1;

        uint32_t ph[8][2], pl[8][2];
        float ls0 = 0.f, ls1 = 0.f;
        #pragma unroll
        for (int ni = 0; ni < 8; ++ni) {
            float p00 = ex2f((sacc[ni][0] - mn0) * L2E);
            float p01 = ex2f((sacc[ni][1] - mn0) * L2E);
            float p10 = ex2f((sacc[ni][2] - mn1) * L2E);
            float p11 = ex2f((sacc[ni][3] - mn1) * L2E);
            ls0 += p00 + p01;
            ls1 += p10 + p11;
            uint32_t hp0 = packbf(p00, p01);
            uint32_t hp1 = packbf(p10, p11);
            ph[ni][0] = hp0;
            ph[ni][1] = hp1;
            pl[ni][0] = packbf(p00 - lobf(hp0), p01 - hibf(hp0));
            pl[ni][1] = packbf(p10 - lobf(hp1), p11 - hibf(hp1));
        }
        ls0 += __shfl_xor_sync(0xffffffffu, ls0, 1);
        ls0 += __shfl_xor_sync(0xffffffffu, ls0, 2);
        ls1 += __shfl_xor_sync(0xffffffffu, ls1, 1);
        ls1 += __shfl_xor_sync(0xffffffffu, ls1, 2);
        l0 = l0 * al0 + ls0;
        l1 = l1 * al1 + ls1;

        #pragma unroll
        for (int f = 0; f < 16; ++f) {
            oacc[f][0] *= al0; oacc[f][1] *= al0;
            oacc[f][2] *= al1; oacc[f][3] *= al1;
        }

        #pragma unroll
        for (int kf = 0; kf < 4; ++kf) {
            uint32_t aPh[4] = { ph[2*kf][0], ph[2*kf][1], ph[2*kf+1][0], ph[2*kf+1][1] };
            uint32_t aPl[4] = { pl[2*kf][0], pl[2*kf][1], pl[2*kf+1][0], pl[2*kf+1][1] };
            #pragma unroll
            for (int nd = 0; nd < 8; ++nd) {
                const uint32_t sub = (nd >> 2) * 8192;
                const uint32_t dd = (nd & 3) * 16;
                const uint32_t kvr = kf * 16 + (vM & 1) * 8 + vR;
                const uint32_t dc = dd + (vM >> 1) * 8;
                const uint32_t voff = SMEM_SWIZZLE_128B(kvr * 128 + dc * 2);
                uint32_t bh4[4], bl4[4];
                ldsm_x4t(bh4, kvb + KV_VH + sub + voff);
                ldsm_x4t(bl4, kvb + KV_VL + sub + voff);
                mma16816(oacc[2*nd],     aPh, bh4);
                mma16816(oacc[2*nd],     aPh, bl4);
                mma16816(oacc[2*nd],     aPl, bh4);
                mma16816(oacc[2*nd + 1], aPh, bh4 + 2);
                mma16816(oacc[2*nd + 1], aPh, bl4 + 2);
                mma16816(oacc[2*nd + 1], aPl, bh4 + 2);
            }
        }

        __syncthreads();
        if (kt + 2 < 32) { load_kv(kt + 2, kt & 1); CP_COMMIT(); }
    }

    const float inv0 = 1.f / l0, inv1 = 1.f / l1;
    const int rQuad = lane >> 2, cPair = (lane & 3) * 2;
    const size_t row0 = qrow0 + w * 16 + rQuad;
    #pragma unroll
    for (int f = 0; f < 16; ++f) {
        int d = f * 8 + cPair;
        float o00 = oacc[f][0] * inv0, o01 = oacc[f][1] * inv0;
        float o10 = oacc[f][2] * inv1, o11 = oacc[f][3] * inv1;
        size_t i0 = (row0 * E_ + hcol + d) >> 1;
        size_t i1 = ((row0 + 8) * E_ + hcol + d) >> 1;
        uint32_t h0 = packbf(o00, o01);
        uint32_t h1 = packbf(o10, o11);
        ((uint32_t*)Chi)[i0] = h0;
        ((uint32_t*)Chi)[i1] = h1;
        ((uint32_t*)Clo)[i0] = packbf(o00 - lobf(h0), o01 - hibf(h0));
        ((uint32_t*)Clo)[i1] = packbf(o10 - lobf(h1), o11 - hibf(h1));
    }
}

// ---------------------------------------------------------------------------
extern "C" void kernel_launch(void* const* d_in, const int* in_sizes, int n_in,
                              void* d_out, int out_size)
{
    const float* query  = (const float*)d_in[0];
    const float* key_in = (const float*)d_in[1];
    const float* value  = (const float*)d_in[2];
    const float* Wq = (const float*)d_in[3];
    const float* bq = (const float*)d_in[4];
    const float* Wk = (const float*)d_in[5];
    const float* bk = (const float*)d_in[6];
    const float* Wv = (const float*)d_in[7];
    const float* bv = (const float*)d_in[8];
    const float* Wo = (const float*)d_in[9];
    const float* bo = (const float*)d_in[10];
    float* out = (float*)d_out;

    __nv_bfloat16 *Ahi, *Alo, *Whi, *Wlo, *Phi, *Plo, *Chi, *Clo;
    cudaGetSymbolAddress((void**)&Ahi, g_Ahi);
    cudaGetSymbolAddress((void**)&Alo, g_Alo);
    cudaGetSymbolAddress((void**)&Whi, g_Whi);
    cudaGetSymbolAddress((void**)&Wlo, g_Wlo);
    cudaGetSymbolAddress((void**)&Phi, g_Phi);
    cudaGetSymbolAddress((void**)&Plo, g_Plo);
    cudaGetSymbolAddress((void**)&Chi, g_Chi);
    cudaGetSymbolAddress((void**)&Clo, g_Clo);

    cudaFuncSetAttribute(flash_mma_kernel,
                         cudaFuncAttributeMaxDynamicSharedMemorySize, FL_SMEM);
    cudaFuncSetAttribute(gemm_proj3_kernel,
                         cudaFuncAttributeMaxDynamicSharedMemorySize, GEMM_SMEM);
    cudaFuncSetAttribute(gemm_out_kernel,
                         cudaFuncAttributeMaxDynamicSharedMemorySize, GEMM_SMEM);

    const dim3 cw(E_ / 32, E_ / 32);
    const int  sa = (MROWS * E_ / 4) / 256;
    const dim3 g3(E_ / 128, MROWS / 128, 3);   // batched projections
    const dim3 gg(E_ / 128, MROWS / 128);
    const dim3 fg(S_ / 128, H_, B_);

    // All conversions up front (independent; includes Wo)
    convW_kernel<<<cw, 256>>>(Wq, Whi + 0 * EE, Wlo + 0 * EE);
    convW_kernel<<<cw, 256>>>(Wk, Whi + 1 * EE, Wlo + 1 * EE);
    convW_kernel<<<cw, 256>>>(Wv, Whi + 2 * EE, Wlo + 2 * EE);
    convW_kernel<<<cw, 256>>>(Wo, Whi + 3 * EE, Wlo + 3 * EE);
    splitA_kernel<<<sa, 256>>>(query,  Ahi + 0 * ME, Alo + 0 * ME);
    splitA_kernel<<<sa, 256>>>(key_in, Ahi + 1 * ME, Alo + 1 * ME);
    splitA_kernel<<<sa, 256>>>(value,  Ahi + 2 * ME, Alo + 2 * ME);

    // Q,K,V projections in ONE launch (1536 CTAs — kills wave tail)
    gemm_proj3_kernel<<<g3, 256, GEMM_SMEM>>>(Ahi, Alo, Whi, Wlo,
                                              bq, bk, bv, Phi, Plo);

    // Attention -> split bf16 context
    flash_mma_kernel<<<fg, 256, FL_SMEM>>>(
        Phi + 0 * ME, Plo + 0 * ME,
        Phi + 1 * ME, Plo + 1 * ME,
        Phi + 2 * ME, Plo + 2 * ME, Chi, Clo);

    // Output projection -> fp32 out
    gemm_out_kernel<<<gg, 256, GEMM_SMEM>>>(Chi, Clo, Whi + 3 * EE, Wlo + 3 * EE,
                                            bo, out);
}